// round 1
// baseline (speedup 1.0000x reference)
#include <cuda_runtime.h>
#include <cuda_bf16.h>
#include <math.h>

// ---------------------------------------------------------------------------
// StatefulCausalAttention  (B=1, H=16, T=2304=128+2048+128, D=1024, dk=dv=64)
//
// Phase 1: projection GEMM  C[2304,3072] = X @ W_eff  (+ fused L2 norm,
//          q additionally scaled by scaling_factor[h]*log2(e))
// Phase 2: fp32 flash attention with causal + state mask (tile-aligned).
//
// Both GEMM microkernels use packed fma.rn.f32x2 (2 FMA/lane/instr).
// ---------------------------------------------------------------------------

#define T_TOT 2304
#define D_IN  1024
#define NH    16

// scratch for normalized q (pre-scaled), k, v : [H][T][64]
__device__ float g_Q[NH * T_TOT * 64];
__device__ float g_K[NH * T_TOT * 64];
__device__ float g_V[NH * T_TOT * 64];

// ---- packed f32x2 helpers (PTX-only path; ptxas never emits these) --------
typedef unsigned long long f32x2;

__device__ __forceinline__ f32x2 fma2(f32x2 a, f32x2 b, f32x2 c) {
    f32x2 d;
    asm("fma.rn.f32x2 %0, %1, %2, %3;" : "=l"(d) : "l"(a), "l"(b), "l"(c));
    return d;
}
__device__ __forceinline__ f32x2 mul2(f32x2 a, f32x2 b) {
    f32x2 d;
    asm("mul.rn.f32x2 %0, %1, %2;" : "=l"(d) : "l"(a), "l"(b));
    return d;
}
__device__ __forceinline__ f32x2 dup2(float x) {
    f32x2 d;
    asm("mov.b64 %0, {%1, %1};" : "=l"(d) : "f"(x));
    return d;
}
__device__ __forceinline__ void unpack2(f32x2 v, float& a, float& b) {
    asm("mov.b64 {%0, %1}, %2;" : "=f"(a), "=f"(b) : "l"(v));
}

// ---------------------------------------------------------------------------
// Projection kernel: BM=128 rows x BN=64 cols (one head, one of q/k/v),
// BK=16, 128 threads, 8x8 microtile. Epilogue: row L2-norm over the 64 cols
// (full head dim lives inside the block), q gets sf[h]*log2e folded in.
// Row tiles of 128 align exactly with segment boundaries (0..127 state,
// 128..2175 mid, 2176..2303 state).
// ---------------------------------------------------------------------------
__global__ __launch_bounds__(128) void proj_kernel(
    const float* __restrict__ x,
    const float* __restrict__ Wq,  const float* __restrict__ Wk,  const float* __restrict__ Wv,
    const float* __restrict__ Wqs, const float* __restrict__ Wks, const float* __restrict__ Wvs,
    const float* __restrict__ sf)
{
    __shared__ float AsT[16][128];   // [k][m]  (transposed X tile)
    __shared__ float Bs[16][64];     // [k][n]

    const int tid  = threadIdx.x;
    const int bx   = blockIdx.x;     // 0..47 : type*16 + head
    const int by   = blockIdx.y;     // 0..17 : row tile
    const int row0 = by * 128;
    const int type = bx >> 4;        // 0=q 1=k 2=v
    const int h    = bx & 15;
    const bool state = (by == 0) || (by == 17);

    const float* W;
    if (type == 0)      W = state ? Wqs : Wq;
    else if (type == 1) W = state ? Wks : Wk;
    else                W = state ? Wvs : Wv;
    W += (size_t)h * D_IN * 64;

    const int ty = tid >> 3, tx = tid & 7;
    const int i0 = ty * 8,  j0 = tx * 8;

    f32x2 acc[8][4];
#pragma unroll
    for (int r = 0; r < 8; ++r)
#pragma unroll
        for (int c = 0; c < 4; ++c) acc[r][c] = 0ull;

    const float4* xrow = (const float4*)(x + (size_t)(row0 + tid) * D_IN);

    for (int k0 = 0; k0 < D_IN; k0 += 16) {
        // load X tile transposed: thread tid owns row (row0+tid)
#pragma unroll
        for (int q4 = 0; q4 < 4; ++q4) {
            float4 v = xrow[(k0 >> 2) + q4];
            AsT[q4 * 4 + 0][tid] = v.x;
            AsT[q4 * 4 + 1][tid] = v.y;
            AsT[q4 * 4 + 2][tid] = v.z;
            AsT[q4 * 4 + 3][tid] = v.w;
        }
        // load W tile: 256 float4 slots, 2 per thread
#pragma unroll
        for (int p = 0; p < 2; ++p) {
            int pos = tid + p * 128;
            int kk = pos >> 4, c4 = pos & 15;
            *(float4*)&Bs[kk][c4 * 4] =
                *(const float4*)(W + (size_t)(k0 + kk) * 64 + c4 * 4);
        }
        __syncthreads();

#pragma unroll
        for (int kk = 0; kk < 16; ++kk) {
            float4 a0 = *(const float4*)&AsT[kk][i0];
            float4 a1 = *(const float4*)&AsT[kk][i0 + 4];
            ulonglong2 bA = *(const ulonglong2*)&Bs[kk][j0];
            ulonglong2 bB = *(const ulonglong2*)&Bs[kk][j0 + 4];
            float a[8] = {a0.x, a0.y, a0.z, a0.w, a1.x, a1.y, a1.z, a1.w};
#pragma unroll
            for (int r = 0; r < 8; ++r) {
                f32x2 ad = dup2(a[r]);
                acc[r][0] = fma2(ad, bA.x, acc[r][0]);
                acc[r][1] = fma2(ad, bA.y, acc[r][1]);
                acc[r][2] = fma2(ad, bB.x, acc[r][2]);
                acc[r][3] = fma2(ad, bB.y, acc[r][3]);
            }
        }
        __syncthreads();
    }

    // epilogue: L2 norm per row (reduce across the 8 tx lanes, width-8 shfl)
    float* dst = (type == 0) ? g_Q : (type == 1) ? g_K : g_V;
    dst += (size_t)h * T_TOT * 64;
    const float qscale = (type == 0) ? sf[h] * 1.44269504088896340736f : 1.0f;

#pragma unroll
    for (int r = 0; r < 8; ++r) {
        float e[8];
#pragma unroll
        for (int c = 0; c < 4; ++c) unpack2(acc[r][c], e[2 * c], e[2 * c + 1]);
        float ss = 0.f;
#pragma unroll
        for (int c = 0; c < 8; ++c) ss += e[c] * e[c];
        ss += __shfl_xor_sync(0xffffffffu, ss, 1, 8);
        ss += __shfl_xor_sync(0xffffffffu, ss, 2, 8);
        ss += __shfl_xor_sync(0xffffffffu, ss, 4, 8);
        float inv = qscale / fmaxf(sqrtf(ss), 1e-12f);

        int row = row0 + i0 + r;
        float4 w0 = make_float4(e[0] * inv, e[1] * inv, e[2] * inv, e[3] * inv);
        float4 w1 = make_float4(e[4] * inv, e[5] * inv, e[6] * inv, e[7] * inv);
        *(float4*)(dst + (size_t)row * 64 + j0)     = w0;
        *(float4*)(dst + (size_t)row * 64 + j0 + 4) = w1;
    }
}

// ---------------------------------------------------------------------------
// Flash attention: block = (head h, q-tile of 128 rows). kv tiles of 64.
// it in 0..17; kv tiles jt in [jt0, 2*it+1] with jt0=2 for it==17 (state-tail
// rows may not see leading-state cols — tile-exact since 2176=17*128,128=2*64).
// Per-element causal mask only needed for jt >= 2*it.
// q pre-scaled by sf*log2e so softmax runs in exp2 domain.
// 128 threads, 8x8 microtiles for both S=QK^T and O+=PV.  96KB dynamic smem.
// Blocks launched with it descending (heaviest first) for load balance.
// ---------------------------------------------------------------------------
__global__ __launch_bounds__(128) void attn_kernel(float* __restrict__ out)
{
    extern __shared__ float sm[];
    float* QsT = sm;                       // [64][128]  q transposed [d][i]
    float* KsT = sm + 64 * 128;            // [64][64]   k transposed [d][j]
    float* Vs  = KsT + 64 * 64;            // [64][64]   v row-major  [j][dv]
    float* PsT = Vs + 64 * 64;             // [64][128]  p transposed [j][i]

    const int h  = blockIdx.y;
    const int it = 17 - (int)blockIdx.x;   // descending work order
    const int rb = it * 128;
    const int tid = threadIdx.x;
    const int ty = tid >> 3, tx = tid & 7;
    const int i0 = ty * 8, j0 = tx * 8;    // j0 doubles as dv offset in PV

    const float* Qg = g_Q + (size_t)h * T_TOT * 64;
    const float* Kg = g_K + (size_t)h * T_TOT * 64;
    const float* Vg = g_V + (size_t)h * T_TOT * 64;

    // load Q tile transposed (thread owns one row)
    {
        const float4* qr = (const float4*)(Qg + (size_t)(rb + tid) * 64);
#pragma unroll
        for (int q4 = 0; q4 < 16; ++q4) {
            float4 v = qr[q4];
            QsT[(q4 * 4 + 0) * 128 + tid] = v.x;
            QsT[(q4 * 4 + 1) * 128 + tid] = v.y;
            QsT[(q4 * 4 + 2) * 128 + tid] = v.z;
            QsT[(q4 * 4 + 3) * 128 + tid] = v.w;
        }
    }

    f32x2 o2[8][4];
    float m[8], l[8];
#pragma unroll
    for (int r = 0; r < 8; ++r) {
        m[r] = -INFINITY; l[r] = 0.f;
#pragma unroll
        for (int c = 0; c < 4; ++c) o2[r][c] = 0ull;
    }

    const int jt0 = (it == 17) ? 2 : 0;
    const int jt1 = 2 * it + 1;

    for (int jt = jt0; jt <= jt1; ++jt) {
        const int cb = jt * 64;
        __syncthreads();   // previous iteration's PV reads done before reload

        // K tile transposed: 2 halves of d per thread-group
        {
            int jr = tid & 63;
            int dh = (tid >> 6) * 32;
            const float4* kr = (const float4*)(Kg + (size_t)(cb + jr) * 64 + dh);
#pragma unroll
            for (int q4 = 0; q4 < 8; ++q4) {
                float4 v = kr[q4];
                int d = dh + q4 * 4;
                KsT[(d + 0) * 64 + jr] = v.x;
                KsT[(d + 1) * 64 + jr] = v.y;
                KsT[(d + 2) * 64 + jr] = v.z;
                KsT[(d + 3) * 64 + jr] = v.w;
            }
        }
        // V tile (row-major, straight copy)
#pragma unroll
        for (int p = 0; p < 8; ++p) {
            int idx = tid + p * 128;         // over 1024 float4
            int rr = idx >> 4, c4 = idx & 15;
            *(float4*)&Vs[rr * 64 + c4 * 4] =
                *(const float4*)(Vg + (size_t)(cb + rr) * 64 + c4 * 4);
        }
        __syncthreads();

        // ---- S = Q K^T  (scaled q already in exp2 domain) ----
        f32x2 s2[8][4];
#pragma unroll
        for (int r = 0; r < 8; ++r)
#pragma unroll
            for (int c = 0; c < 4; ++c) s2[r][c] = 0ull;

#pragma unroll 4
        for (int d = 0; d < 64; ++d) {
            float4 a0 = *(const float4*)&QsT[d * 128 + i0];
            float4 a1 = *(const float4*)&QsT[d * 128 + i0 + 4];
            ulonglong2 bA = *(const ulonglong2*)&KsT[d * 64 + j0];
            ulonglong2 bB = *(const ulonglong2*)&KsT[d * 64 + j0 + 4];
            float a[8] = {a0.x, a0.y, a0.z, a0.w, a1.x, a1.y, a1.z, a1.w};
#pragma unroll
            for (int r = 0; r < 8; ++r) {
                f32x2 ad = dup2(a[r]);
                s2[r][0] = fma2(ad, bA.x, s2[r][0]);
                s2[r][1] = fma2(ad, bA.y, s2[r][1]);
                s2[r][2] = fma2(ad, bB.x, s2[r][2]);
                s2[r][3] = fma2(ad, bB.y, s2[r][3]);
            }
        }

        // ---- online softmax ----
        const bool needMask = (jt >= 2 * it);
#pragma unroll
        for (int r = 0; r < 8; ++r) {
            float e[8];
#pragma unroll
            for (int c = 0; c < 4; ++c) unpack2(s2[r][c], e[2 * c], e[2 * c + 1]);
            if (needMask) {
                int ig = rb + i0 + r;
#pragma unroll
                for (int c = 0; c < 8; ++c)
                    if (cb + j0 + c > ig) e[c] = -1e30f;
            }
            float mx = e[0];
#pragma unroll
            for (int c = 1; c < 8; ++c) mx = fmaxf(mx, e[c]);
            mx = fmaxf(mx, __shfl_xor_sync(0xffffffffu, mx, 1, 8));
            mx = fmaxf(mx, __shfl_xor_sync(0xffffffffu, mx, 2, 8));
            mx = fmaxf(mx, __shfl_xor_sync(0xffffffffu, mx, 4, 8));
            float mnew = fmaxf(m[r], mx);
            float corr = exp2f(m[r] - mnew);
            m[r] = mnew;

            float rs = 0.f;
#pragma unroll
            for (int c = 0; c < 8; ++c) {
                float p = exp2f(e[c] - mnew);
                rs += p;
                e[c] = p;
            }
            rs += __shfl_xor_sync(0xffffffffu, rs, 1, 8);
            rs += __shfl_xor_sync(0xffffffffu, rs, 2, 8);
            rs += __shfl_xor_sync(0xffffffffu, rs, 4, 8);
            l[r] = l[r] * corr + rs;

            f32x2 cc = dup2(corr);
#pragma unroll
            for (int c = 0; c < 4; ++c) o2[r][c] = mul2(o2[r][c], cc);

#pragma unroll
            for (int c = 0; c < 8; ++c)
                PsT[(j0 + c) * 128 + i0 + r] = e[c];
        }
        __syncthreads();

        // ---- O += P V ----
#pragma unroll 4
        for (int j = 0; j < 64; ++j) {
            float4 a0 = *(const float4*)&PsT[j * 128 + i0];
            float4 a1 = *(const float4*)&PsT[j * 128 + i0 + 4];
            ulonglong2 bA = *(const ulonglong2*)&Vs[j * 64 + j0];
            ulonglong2 bB = *(const ulonglong2*)&Vs[j * 64 + j0 + 4];
            float a[8] = {a0.x, a0.y, a0.z, a0.w, a1.x, a1.y, a1.z, a1.w};
#pragma unroll
            for (int r = 0; r < 8; ++r) {
                f32x2 ad = dup2(a[r]);
                o2[r][0] = fma2(ad, bA.x, o2[r][0]);
                o2[r][1] = fma2(ad, bA.y, o2[r][1]);
                o2[r][2] = fma2(ad, bB.x, o2[r][2]);
                o2[r][3] = fma2(ad, bB.y, o2[r][3]);
            }
        }
    }

    // ---- normalize and store ----
    float* og = out + (size_t)h * T_TOT * 64;
#pragma unroll
    for (int r = 0; r < 8; ++r) {
        float invl = 1.0f / l[r];
        float e[8];
#pragma unroll
        for (int c = 0; c < 4; ++c) unpack2(o2[r][c], e[2 * c], e[2 * c + 1]);
        int row = rb + i0 + r;
        float4 w0 = make_float4(e[0] * invl, e[1] * invl, e[2] * invl, e[3] * invl);
        float4 w1 = make_float4(e[4] * invl, e[5] * invl, e[6] * invl, e[7] * invl);
        *(float4*)(og + (size_t)row * 64 + j0)     = w0;
        *(float4*)(og + (size_t)row * 64 + j0 + 4) = w1;
    }
}

// ---------------------------------------------------------------------------
extern "C" void kernel_launch(void* const* d_in, const int* in_sizes, int n_in,
                              void* d_out, int out_size)
{
    (void)in_sizes; (void)n_in; (void)out_size;
    const float* x   = (const float*)d_in[0];
    const float* Wq  = (const float*)d_in[1];
    const float* Wk  = (const float*)d_in[2];
    const float* Wv  = (const float*)d_in[3];
    const float* Wqs = (const float*)d_in[4];
    const float* Wks = (const float*)d_in[5];
    const float* Wvs = (const float*)d_in[6];
    const float* sf  = (const float*)d_in[7];
    float* out = (float*)d_out;

    cudaFuncSetAttribute(attn_kernel,
                         cudaFuncAttributeMaxDynamicSharedMemorySize, 98304);

    proj_kernel<<<dim3(48, 18), 128>>>(x, Wq, Wk, Wv, Wqs, Wks, Wvs, sf);
    attn_kernel<<<dim3(18, 16), 128, 98304>>>(out);
}

// round 3
// speedup vs baseline: 1.0115x; 1.0115x over previous
#include <cuda_runtime.h>
#include <cuda_bf16.h>
#include <math.h>
#include <cstdint>

// ---------------------------------------------------------------------------
// StatefulCausalAttention  (B=1, H=16, T=2304=128+2048+128, D=1024, dk=dv=64)
// R3: projection via mma.sync bf16 (hi/lo split, 3-term) — arch-agnostic
//     tensor path (tcgen05 PTX does not compile: harness targets compute_103,
//     not sm_103a). Attention: scalar f32x2, 256 thr, fixed-max softmax.
// ---------------------------------------------------------------------------

#define T_TOT 2304
#define D_IN  1024
#define NH    16

__device__ float g_Q[NH * T_TOT * 64];
__device__ float g_K[NH * T_TOT * 64];
__device__ float g_V[NH * T_TOT * 64];

// split operands for projection
__device__ __nv_bfloat16 g_Xhi[T_TOT * D_IN];
__device__ __nv_bfloat16 g_Xlo[T_TOT * D_IN];
// [mat(6)=q,qs,k,ks,v,vs][h(16)][n(64)][k(1024)]
__device__ __nv_bfloat16 g_Bhi[6 * 16 * 64 * 1024];
__device__ __nv_bfloat16 g_Blo[6 * 16 * 64 * 1024];

// ============================ helpers ======================================
typedef unsigned long long f32x2;

__device__ __forceinline__ f32x2 fma2(f32x2 a, f32x2 b, f32x2 c) {
    f32x2 d; asm("fma.rn.f32x2 %0, %1, %2, %3;" : "=l"(d) : "l"(a), "l"(b), "l"(c)); return d;
}
__device__ __forceinline__ f32x2 dup2(float x) {
    f32x2 d; asm("mov.b64 %0, {%1, %1};" : "=l"(d) : "f"(x)); return d;
}
__device__ __forceinline__ void unpack2(f32x2 v, float& a, float& b) {
    asm("mov.b64 {%0, %1}, %2;" : "=f"(a), "=f"(b) : "l"(v));
}
__device__ __forceinline__ float ex2f_fast(float x) {
    float y; asm("ex2.approx.f32 %0, %1;" : "=f"(y) : "f"(x)); return y;
}
__device__ __forceinline__ void mma16816(float* c, const uint32_t* a,
                                         uint32_t b0, uint32_t b1) {
    asm("mma.sync.aligned.m16n8k16.row.col.f32.bf16.bf16.f32 "
        "{%0,%1,%2,%3}, {%4,%5,%6,%7}, {%8,%9}, {%0,%1,%2,%3};"
        : "+f"(c[0]), "+f"(c[1]), "+f"(c[2]), "+f"(c[3])
        : "r"(a[0]), "r"(a[1]), "r"(a[2]), "r"(a[3]), "r"(b0), "r"(b1));
}
__device__ __forceinline__ void split_bf16(float f, __nv_bfloat16& hi, __nv_bfloat16& lo) {
    hi = __float2bfloat16(f);
    lo = __float2bfloat16(f - __bfloat162float(hi));
}

// ============================ prep: x -> hi/lo bf16 ========================
__global__ __launch_bounds__(256) void xconv_kernel(const float* __restrict__ x)
{
    int idx = blockIdx.x * 256 + threadIdx.x;       // 0..589823 (x float4s)
    float4 v = ((const float4*)x)[idx];
    __nv_bfloat16 hs[4], ls[4];
    split_bf16(v.x, hs[0], ls[0]);
    split_bf16(v.y, hs[1], ls[1]);
    split_bf16(v.z, hs[2], ls[2]);
    split_bf16(v.w, hs[3], ls[3]);
    *(uint2*)&g_Xhi[(size_t)idx * 4] = *(uint2*)hs;
    *(uint2*)&g_Xlo[(size_t)idx * 4] = *(uint2*)ls;
}

// ============================ prep: W transpose + split ====================
// W[mat][h]: [1024 k][64 n] f32  ->  g_B{hi,lo}[mat*16+h][64 n][1024 k] bf16
__global__ __launch_bounds__(256) void wconv_kernel(
    const float* __restrict__ Wq,  const float* __restrict__ Wk,  const float* __restrict__ Wv,
    const float* __restrict__ Wqs, const float* __restrict__ Wks, const float* __restrict__ Wvs)
{
    __shared__ float t[64][65];
    const int bk = blockIdx.x;          // k-tile of 64
    const int mh = blockIdx.y;          // 0..95
    const int mat = mh >> 4, h = mh & 15;
    const float* W;
    switch (mat) {
        case 0: W = Wq;  break; case 1: W = Wqs; break;
        case 2: W = Wk;  break; case 3: W = Wks; break;
        case 4: W = Wv;  break; default: W = Wvs; break;
    }
    W += (size_t)h * D_IN * 64;
    const int k0 = bk * 64;
    const int tid = threadIdx.x;
#pragma unroll
    for (int p = 0; p < 4; ++p) {
        int slot = tid + p * 256;
        int kr = slot >> 4, f4 = slot & 15;
        float4 v = *(const float4*)(W + (size_t)(k0 + kr) * 64 + f4 * 4);
        t[kr][f4 * 4 + 0] = v.x; t[kr][f4 * 4 + 1] = v.y;
        t[kr][f4 * 4 + 2] = v.z; t[kr][f4 * 4 + 3] = v.w;
    }
    __syncthreads();
    const size_t base = (size_t)mh * 64 * 1024;
#pragma unroll
    for (int p = 0; p < 4; ++p) {
        int slot = tid + p * 256;
        int n = slot >> 4, f4 = slot & 15;
        __nv_bfloat16 hs[4], ls[4];
#pragma unroll
        for (int j = 0; j < 4; ++j)
            split_bf16(t[f4 * 4 + j][n], hs[j], ls[j]);
        size_t o = base + (size_t)n * 1024 + k0 + f4 * 4;
        *(uint2*)&g_Bhi[o] = *(uint2*)hs;
        *(uint2*)&g_Blo[o] = *(uint2*)ls;
    }
}

// ============================ projection (mma.sync bf16) ===================
// block = (type*16+h, row-tile of 128). 256 thr, warp w owns rows w*16..+15.
// K chunks of 32 (2 ksteps), double-buffered smem, 3 split-term mmas.
// Epilogue: row L2 norm, q scaled by sf[h]*log2e.
//
// smem stage (30720 B): Ahi[128][40bf16] @0, Alo @10240, Bhi[64][40] @20480,
// Blo @25600. Row pad 40 bf16 (80 B) -> conflict-free frag LDS.
#define PROJ_SMEM 61440

__global__ __launch_bounds__(256, 2) void proj_kernel(const float* __restrict__ sf)
{
    extern __shared__ char smc[];
    const int bx   = blockIdx.x;
    const int type = bx >> 4;            // 0=q 1=k 2=v
    const int h    = bx & 15;
    const int by   = blockIdx.y;
    const int row0 = by * 128;
    const int state = (by == 0 || by == 17) ? 1 : 0;
    const int mat  = type * 2 + state;

    const __nv_bfloat16* Bh = g_Bhi + ((size_t)(mat * 16 + h)) * 64 * 1024;
    const __nv_bfloat16* Bl = g_Blo + ((size_t)(mat * 16 + h)) * 64 * 1024;
    const __nv_bfloat16* Xh = g_Xhi + (size_t)row0 * D_IN;
    const __nv_bfloat16* Xl = g_Xlo + (size_t)row0 * D_IN;

    const int tid  = threadIdx.x;
    const int warp = tid >> 5, lane = tid & 31;
    const int r = lane >> 2, q = lane & 3;

    float acc[8][4];
#pragma unroll
    for (int nt = 0; nt < 8; ++nt)
#pragma unroll
        for (int j = 0; j < 4; ++j) acc[nt][j] = 0.f;

    auto load_chunk = [&](int c) {
        const int k0 = c * 32;
        char* st = smc + (c & 1) * 30720;
#pragma unroll
        for (int i = 0; i < 6; ++i) {
            int slot = tid + i * 256;
            if (slot < 1024) {                       // A tiles (hi, lo)
                int term = slot >> 9;
                int s = slot & 511, m = s >> 2, f = s & 3;
                const __nv_bfloat16* src = (term ? Xl : Xh) + (size_t)m * D_IN + k0 + f * 8;
                *(uint4*)(st + term * 10240 + m * 80 + f * 16) = *(const uint4*)src;
            } else {                                  // B tiles (hi, lo)
                int s2 = slot - 1024;
                int term = s2 >> 8;
                int s = s2 & 255, n = s >> 2, f = s & 3;
                const __nv_bfloat16* src = (term ? Bl : Bh) + (size_t)n * 1024 + k0 + f * 8;
                *(uint4*)(st + 20480 + term * 5120 + n * 80 + f * 16) = *(const uint4*)src;
            }
        }
    };

    load_chunk(0);
    __syncthreads();

    for (int c = 0; c < 32; ++c) {
        if (c + 1 < 32) load_chunk(c + 1);
        const char* st = smc + (c & 1) * 30720;
        const int arow = warp * 16 + r;
#pragma unroll
        for (int ks = 0; ks < 2; ++ks) {
            const int kb = ks * 16 + q * 2;
            uint32_t ah[4], al[4];
            ah[0] = *(const uint32_t*)(st + (arow    ) * 80 + kb * 2);
            ah[1] = *(const uint32_t*)(st + (arow + 8) * 80 + kb * 2);
            ah[2] = *(const uint32_t*)(st + (arow    ) * 80 + (kb + 8) * 2);
            ah[3] = *(const uint32_t*)(st + (arow + 8) * 80 + (kb + 8) * 2);
            al[0] = *(const uint32_t*)(st + 10240 + (arow    ) * 80 + kb * 2);
            al[1] = *(const uint32_t*)(st + 10240 + (arow + 8) * 80 + kb * 2);
            al[2] = *(const uint32_t*)(st + 10240 + (arow    ) * 80 + (kb + 8) * 2);
            al[3] = *(const uint32_t*)(st + 10240 + (arow + 8) * 80 + (kb + 8) * 2);
            const char* bb = st + 20480;
#pragma unroll
            for (int nt = 0; nt < 8; ++nt) {
                const int nrow = nt * 8 + r;
                uint32_t bh0 = *(const uint32_t*)(bb + nrow * 80 + kb * 2);
                uint32_t bh1 = *(const uint32_t*)(bb + nrow * 80 + (kb + 8) * 2);
                uint32_t bl0 = *(const uint32_t*)(bb + 5120 + nrow * 80 + kb * 2);
                uint32_t bl1 = *(const uint32_t*)(bb + 5120 + nrow * 80 + (kb + 8) * 2);
                mma16816(acc[nt], ah, bh0, bh1);   // hi*hi
                mma16816(acc[nt], ah, bl0, bl1);   // hi*lo
                mma16816(acc[nt], al, bh0, bh1);   // lo*hi
            }
        }
        __syncthreads();
    }

    // ---- epilogue: L2 norm per row ----
    float ss0 = 0.f, ss1 = 0.f;
#pragma unroll
    for (int nt = 0; nt < 8; ++nt) {
        ss0 += acc[nt][0] * acc[nt][0] + acc[nt][1] * acc[nt][1];
        ss1 += acc[nt][2] * acc[nt][2] + acc[nt][3] * acc[nt][3];
    }
    ss0 += __shfl_xor_sync(0xffffffffu, ss0, 1, 4);
    ss0 += __shfl_xor_sync(0xffffffffu, ss0, 2, 4);
    ss1 += __shfl_xor_sync(0xffffffffu, ss1, 1, 4);
    ss1 += __shfl_xor_sync(0xffffffffu, ss1, 2, 4);

    const float qs = (type == 0) ? sf[h] * 1.44269504088896340736f : 1.0f;
    const float s0 = qs / fmaxf(sqrtf(ss0), 1e-12f);
    const float s1 = qs / fmaxf(sqrtf(ss1), 1e-12f);

    float* dst = ((type == 0) ? g_Q : (type == 1) ? g_K : g_V)
                 + (size_t)h * T_TOT * 64;
    const int rg = row0 + warp * 16 + r;
#pragma unroll
    for (int nt = 0; nt < 8; ++nt) {
        float2 v0 = make_float2(acc[nt][0] * s0, acc[nt][1] * s0);
        float2 v1 = make_float2(acc[nt][2] * s1, acc[nt][3] * s1);
        *(float2*)(dst + (size_t)(rg    ) * 64 + nt * 8 + q * 2) = v0;
        *(float2*)(dst + (size_t)(rg + 8) * 64 + nt * 8 + q * 2) = v1;
    }
}

// ============================ attention ====================================
// 256 threads, q-tile 128, kv-tile 64, 4x8 microtile, fixed-max softmax
// (|scores*sf*log2e| <= 0.19 since q,k unit vectors; masked -> -1e30 -> 0).
#define PSTRIDE 129
#define ATTN_SMEM ((64 * 128 + 64 * 64 + 64 * 64 + 64 * PSTRIDE) * 4)

__global__ __launch_bounds__(256, 2) void attn_kernel(float* __restrict__ out)
{
    extern __shared__ float sm[];
    float* QsT = sm;                        // [64 d][128 i]
    float* KsT = sm + 64 * 128;             // [64 d][64 j]
    float* Vs  = KsT + 64 * 64;             // [64 j][64 dv]
    float* PsT = Vs + 64 * 64;              // [64 j][PSTRIDE i]

    const int h  = blockIdx.y;
    const int it = 17 - (int)blockIdx.x;
    const int rb = it * 128;
    const int tid = threadIdx.x;
    const int ty = tid >> 3, tx = tid & 7;
    const int i0 = ty * 4, j0 = tx * 8;

    const float* Qg = g_Q + (size_t)h * T_TOT * 64;
    const float* Kg = g_K + (size_t)h * T_TOT * 64;
    const float* Vg = g_V + (size_t)h * T_TOT * 64;

    {
        int row = tid >> 1, half = tid & 1;
        const float4* qr = (const float4*)(Qg + (size_t)(rb + row) * 64 + half * 32);
#pragma unroll
        for (int q4 = 0; q4 < 8; ++q4) {
            float4 v = qr[q4];
            int d = half * 32 + q4 * 4;
            QsT[(d + 0) * 128 + row] = v.x;
            QsT[(d + 1) * 128 + row] = v.y;
            QsT[(d + 2) * 128 + row] = v.z;
            QsT[(d + 3) * 128 + row] = v.w;
        }
    }

    f32x2 o2[4][4];
    float l[4];
#pragma unroll
    for (int r = 0; r < 4; ++r) {
        l[r] = 0.f;
#pragma unroll
        for (int c = 0; c < 4; ++c) o2[r][c] = 0ull;
    }

    const int jt0 = (it == 17) ? 2 : 0;
    const int jt1 = 2 * it + 1;

    for (int jt = jt0; jt <= jt1; ++jt) {
        const int cb = jt * 64;
        __syncthreads();

        {
            int jr = tid & 63;
            int dh = (tid >> 6) * 16;
            const float4* kr = (const float4*)(Kg + (size_t)(cb + jr) * 64 + dh);
#pragma unroll
            for (int q4 = 0; q4 < 4; ++q4) {
                float4 v = kr[q4];
                int d = dh + q4 * 4;
                KsT[(d + 0) * 64 + jr] = v.x;
                KsT[(d + 1) * 64 + jr] = v.y;
                KsT[(d + 2) * 64 + jr] = v.z;
                KsT[(d + 3) * 64 + jr] = v.w;
            }
        }
#pragma unroll
        for (int p = 0; p < 4; ++p) {
            int idx = tid + p * 256;
            int rr = idx >> 4, c4 = idx & 15;
            *(float4*)&Vs[rr * 64 + c4 * 4] =
                *(const float4*)(Vg + (size_t)(cb + rr) * 64 + c4 * 4);
        }
        __syncthreads();

        // ---- S = Q K^T ----
        f32x2 s2[4][4];
#pragma unroll
        for (int r = 0; r < 4; ++r)
#pragma unroll
            for (int c = 0; c < 4; ++c) s2[r][c] = 0ull;

#pragma unroll 4
        for (int d = 0; d < 64; ++d) {
            float4 a = *(const float4*)&QsT[d * 128 + i0];
            ulonglong2 bA = *(const ulonglong2*)&KsT[d * 64 + j0];
            ulonglong2 bB = *(const ulonglong2*)&KsT[d * 64 + j0 + 4];
            float av[4] = {a.x, a.y, a.z, a.w};
#pragma unroll
            for (int r = 0; r < 4; ++r) {
                f32x2 ad = dup2(av[r]);
                s2[r][0] = fma2(ad, bA.x, s2[r][0]);
                s2[r][1] = fma2(ad, bA.y, s2[r][1]);
                s2[r][2] = fma2(ad, bB.x, s2[r][2]);
                s2[r][3] = fma2(ad, bB.y, s2[r][3]);
            }
        }

        // ---- fixed-max softmax (m = 0) ----
        const bool needMask = (jt >= 2 * it);
#pragma unroll
        for (int r = 0; r < 4; ++r) {
            float e[8];
#pragma unroll
            for (int c = 0; c < 4; ++c) unpack2(s2[r][c], e[2 * c], e[2 * c + 1]);
            if (needMask) {
                int ig = rb + i0 + r;
#pragma unroll
                for (int c = 0; c < 8; ++c)
                    if (cb + j0 + c > ig) e[c] = -1e30f;
            }
            float rs = 0.f;
#pragma unroll
            for (int c = 0; c < 8; ++c) {
                float p = ex2f_fast(e[c]);
                rs += p;
                PsT[(j0 + c) * PSTRIDE + i0 + r] = p;
            }
            rs += __shfl_xor_sync(0xffffffffu, rs, 1, 8);
            rs += __shfl_xor_sync(0xffffffffu, rs, 2, 8);
            rs += __shfl_xor_sync(0xffffffffu, rs, 4, 8);
            l[r] += rs;
        }
        __syncthreads();

        // ---- O += P V ----
#pragma unroll 4
        for (int j = 0; j < 64; ++j) {
            const float* pr = &PsT[j * PSTRIDE + i0];
            ulonglong2 bA = *(const ulonglong2*)&Vs[j * 64 + j0];
            ulonglong2 bB = *(const ulonglong2*)&Vs[j * 64 + j0 + 4];
#pragma unroll
            for (int r = 0; r < 4; ++r) {
                f32x2 ad = dup2(pr[r]);
                o2[r][0] = fma2(ad, bA.x, o2[r][0]);
                o2[r][1] = fma2(ad, bA.y, o2[r][1]);
                o2[r][2] = fma2(ad, bB.x, o2[r][2]);
                o2[r][3] = fma2(ad, bB.y, o2[r][3]);
            }
        }
    }

    // ---- normalize and store ----
    float* og = out + (size_t)h * T_TOT * 64;
#pragma unroll
    for (int r = 0; r < 4; ++r) {
        float invl = 1.0f / l[r];
        float e[8];
#pragma unroll
        for (int c = 0; c < 4; ++c) unpack2(o2[r][c], e[2 * c], e[2 * c + 1]);
        int row = rb + i0 + r;
        float4 w0 = make_float4(e[0] * invl, e[1] * invl, e[2] * invl, e[3] * invl);
        float4 w1 = make_float4(e[4] * invl, e[5] * invl, e[6] * invl, e[7] * invl);
        *(float4*)(og + (size_t)row * 64 + j0)     = w0;
        *(float4*)(og + (size_t)row * 64 + j0 + 4) = w1;
    }
}

// ---------------------------------------------------------------------------
extern "C" void kernel_launch(void* const* d_in, const int* in_sizes, int n_in,
                              void* d_out, int out_size)
{
    (void)in_sizes; (void)n_in; (void)out_size;
    const float* x   = (const float*)d_in[0];
    const float* Wq  = (const float*)d_in[1];
    const float* Wk  = (const float*)d_in[2];
    const float* Wv  = (const float*)d_in[3];
    const float* Wqs = (const float*)d_in[4];
    const float* Wks = (const float*)d_in[5];
    const float* Wvs = (const float*)d_in[6];
    const float* sf  = (const float*)d_in[7];
    float* out = (float*)d_out;

    cudaFuncSetAttribute(proj_kernel,
                         cudaFuncAttributeMaxDynamicSharedMemorySize, PROJ_SMEM);
    cudaFuncSetAttribute(attn_kernel,
                         cudaFuncAttributeMaxDynamicSharedMemorySize, ATTN_SMEM);

    xconv_kernel<<<2304, 256>>>(x);
    wconv_kernel<<<dim3(16, 96), 256>>>(Wq, Wk, Wv, Wqs, Wks, Wvs);
    proj_kernel<<<dim3(48, 18), 256, PROJ_SMEM>>>(sf);
    attn_kernel<<<dim3(18, 16), 256, ATTN_SMEM>>>(out);
}

// round 4
// speedup vs baseline: 2.5695x; 2.5403x over previous
#include <cuda_runtime.h>
#include <cuda_bf16.h>
#include <math.h>
#include <cstdint>

// ---------------------------------------------------------------------------
// StatefulCausalAttention  (B=1, H=16, T=2304=128+2048+128, D=1024, dk=dv=64)
// R4: BOTH phases on mma.sync bf16 hi/lo (3-term). Attention is an FA2-style
//     register pipeline: S accumulators are reused directly as PV A-fragments,
//     fixed-max softmax, double-buffered smem + register prefetch.
// ---------------------------------------------------------------------------

#define T_TOT 2304
#define D_IN  1024
#define NH    16

// projection outputs, bf16 hi/lo split
__device__ __nv_bfloat16 g_Qh[NH * T_TOT * 64];   // [h][t][64]  q * sf * log2e
__device__ __nv_bfloat16 g_Ql[NH * T_TOT * 64];
__device__ __nv_bfloat16 g_Kh[NH * T_TOT * 64];   // [h][t][64]
__device__ __nv_bfloat16 g_Kl[NH * T_TOT * 64];
__device__ __nv_bfloat16 g_VTh[NH * 64 * T_TOT];  // [h][dv][t]  (transposed)
__device__ __nv_bfloat16 g_VTl[NH * 64 * T_TOT];

// projection operands
__device__ __nv_bfloat16 g_Xhi[T_TOT * D_IN];
__device__ __nv_bfloat16 g_Xlo[T_TOT * D_IN];
__device__ __nv_bfloat16 g_Bhi[6 * 16 * 64 * 1024];  // [mat][h][n][k]
__device__ __nv_bfloat16 g_Blo[6 * 16 * 64 * 1024];

// ============================ helpers ======================================
__device__ __forceinline__ float ex2f_fast(float x) {
    float y; asm("ex2.approx.f32 %0, %1;" : "=f"(y) : "f"(x)); return y;
}
__device__ __forceinline__ void mma16816(float* c, const uint32_t* a,
                                         uint32_t b0, uint32_t b1) {
    asm("mma.sync.aligned.m16n8k16.row.col.f32.bf16.bf16.f32 "
        "{%0,%1,%2,%3}, {%4,%5,%6,%7}, {%8,%9}, {%0,%1,%2,%3};"
        : "+f"(c[0]), "+f"(c[1]), "+f"(c[2]), "+f"(c[3])
        : "r"(a[0]), "r"(a[1]), "r"(a[2]), "r"(a[3]), "r"(b0), "r"(b1));
}
// pack two f32 -> bf16x2 (lo in lower half, hi in upper half)
__device__ __forceinline__ uint32_t pack_bf16x2(float lo, float hi) {
    uint32_t r;
    asm("cvt.rn.bf16x2.f32 %0, %1, %2;" : "=r"(r) : "f"(hi), "f"(lo));
    return r;
}
__device__ __forceinline__ void split_bf16(float f, __nv_bfloat16& hi, __nv_bfloat16& lo) {
    hi = __float2bfloat16(f);
    lo = __float2bfloat16(f - __bfloat162float(hi));
}

// ============================ prep: x -> hi/lo bf16 ========================
__global__ __launch_bounds__(256) void xconv_kernel(const float* __restrict__ x)
{
    int idx = blockIdx.x * 256 + threadIdx.x;
    float4 v = ((const float4*)x)[idx];
    __nv_bfloat16 hs[4], ls[4];
    split_bf16(v.x, hs[0], ls[0]);
    split_bf16(v.y, hs[1], ls[1]);
    split_bf16(v.z, hs[2], ls[2]);
    split_bf16(v.w, hs[3], ls[3]);
    *(uint2*)&g_Xhi[(size_t)idx * 4] = *(uint2*)hs;
    *(uint2*)&g_Xlo[(size_t)idx * 4] = *(uint2*)ls;
}

// ============================ prep: W transpose + split ====================
__global__ __launch_bounds__(256) void wconv_kernel(
    const float* __restrict__ Wq,  const float* __restrict__ Wk,  const float* __restrict__ Wv,
    const float* __restrict__ Wqs, const float* __restrict__ Wks, const float* __restrict__ Wvs)
{
    __shared__ float t[64][65];
    const int bk = blockIdx.x;
    const int mh = blockIdx.y;
    const int mat = mh >> 4, h = mh & 15;
    const float* W;
    switch (mat) {
        case 0: W = Wq;  break; case 1: W = Wqs; break;
        case 2: W = Wk;  break; case 3: W = Wks; break;
        case 4: W = Wv;  break; default: W = Wvs; break;
    }
    W += (size_t)h * D_IN * 64;
    const int k0 = bk * 64;
    const int tid = threadIdx.x;
#pragma unroll
    for (int p = 0; p < 4; ++p) {
        int slot = tid + p * 256;
        int kr = slot >> 4, f4 = slot & 15;
        float4 v = *(const float4*)(W + (size_t)(k0 + kr) * 64 + f4 * 4);
        t[kr][f4 * 4 + 0] = v.x; t[kr][f4 * 4 + 1] = v.y;
        t[kr][f4 * 4 + 2] = v.z; t[kr][f4 * 4 + 3] = v.w;
    }
    __syncthreads();
    const size_t base = (size_t)mh * 64 * 1024;
#pragma unroll
    for (int p = 0; p < 4; ++p) {
        int slot = tid + p * 256;
        int n = slot >> 4, f4 = slot & 15;
        __nv_bfloat16 hs[4], ls[4];
#pragma unroll
        for (int j = 0; j < 4; ++j)
            split_bf16(t[f4 * 4 + j][n], hs[j], ls[j]);
        size_t o = base + (size_t)n * 1024 + k0 + f4 * 4;
        *(uint2*)&g_Bhi[o] = *(uint2*)hs;
        *(uint2*)&g_Blo[o] = *(uint2*)ls;
    }
}

// ============================ projection (mma.sync bf16) ===================
#define PROJ_SMEM 61440

__global__ __launch_bounds__(256, 2) void proj_kernel(const float* __restrict__ sf)
{
    extern __shared__ char smc[];
    const int bx   = blockIdx.x;
    const int type = bx >> 4;            // 0=q 1=k 2=v
    const int h    = bx & 15;
    const int by   = blockIdx.y;
    const int row0 = by * 128;
    const int state = (by == 0 || by == 17) ? 1 : 0;
    const int mat  = type * 2 + state;

    const __nv_bfloat16* Bh = g_Bhi + ((size_t)(mat * 16 + h)) * 64 * 1024;
    const __nv_bfloat16* Bl = g_Blo + ((size_t)(mat * 16 + h)) * 64 * 1024;
    const __nv_bfloat16* Xh = g_Xhi + (size_t)row0 * D_IN;
    const __nv_bfloat16* Xl = g_Xlo + (size_t)row0 * D_IN;

    const int tid  = threadIdx.x;
    const int warp = tid >> 5, lane = tid & 31;
    const int r = lane >> 2, q = lane & 3;

    float acc[8][4];
#pragma unroll
    for (int nt = 0; nt < 8; ++nt)
#pragma unroll
        for (int j = 0; j < 4; ++j) acc[nt][j] = 0.f;

    auto load_chunk = [&](int c) {
        const int k0 = c * 32;
        char* st = smc + (c & 1) * 30720;
#pragma unroll
        for (int i = 0; i < 6; ++i) {
            int slot = tid + i * 256;
            if (slot < 1024) {
                int term = slot >> 9;
                int s = slot & 511, m = s >> 2, f = s & 3;
                const __nv_bfloat16* src = (term ? Xl : Xh) + (size_t)m * D_IN + k0 + f * 8;
                *(uint4*)(st + term * 10240 + m * 80 + f * 16) = *(const uint4*)src;
            } else {
                int s2 = slot - 1024;
                int term = s2 >> 8;
                int s = s2 & 255, n = s >> 2, f = s & 3;
                const __nv_bfloat16* src = (term ? Bl : Bh) + (size_t)n * 1024 + k0 + f * 8;
                *(uint4*)(st + 20480 + term * 5120 + n * 80 + f * 16) = *(const uint4*)src;
            }
        }
    };

    load_chunk(0);
    __syncthreads();

    for (int c = 0; c < 32; ++c) {
        if (c + 1 < 32) load_chunk(c + 1);
        const char* st = smc + (c & 1) * 30720;
        const int arow = warp * 16 + r;
#pragma unroll
        for (int ks = 0; ks < 2; ++ks) {
            const int kb = ks * 16 + q * 2;
            uint32_t ah[4], al[4];
            ah[0] = *(const uint32_t*)(st + (arow    ) * 80 + kb * 2);
            ah[1] = *(const uint32_t*)(st + (arow + 8) * 80 + kb * 2);
            ah[2] = *(const uint32_t*)(st + (arow    ) * 80 + (kb + 8) * 2);
            ah[3] = *(const uint32_t*)(st + (arow + 8) * 80 + (kb + 8) * 2);
            al[0] = *(const uint32_t*)(st + 10240 + (arow    ) * 80 + kb * 2);
            al[1] = *(const uint32_t*)(st + 10240 + (arow + 8) * 80 + kb * 2);
            al[2] = *(const uint32_t*)(st + 10240 + (arow    ) * 80 + (kb + 8) * 2);
            al[3] = *(const uint32_t*)(st + 10240 + (arow + 8) * 80 + (kb + 8) * 2);
            const char* bb = st + 20480;
#pragma unroll
            for (int nt = 0; nt < 8; ++nt) {
                const int nrow = nt * 8 + r;
                uint32_t bh0 = *(const uint32_t*)(bb + nrow * 80 + kb * 2);
                uint32_t bh1 = *(const uint32_t*)(bb + nrow * 80 + (kb + 8) * 2);
                uint32_t bl0 = *(const uint32_t*)(bb + 5120 + nrow * 80 + kb * 2);
                uint32_t bl1 = *(const uint32_t*)(bb + 5120 + nrow * 80 + (kb + 8) * 2);
                mma16816(acc[nt], ah, bh0, bh1);
                mma16816(acc[nt], ah, bl0, bl1);
                mma16816(acc[nt], al, bh0, bh1);
            }
        }
        __syncthreads();
    }

    // ---- epilogue: L2 norm per row, write bf16 hi/lo (V transposed) ----
    float ss0 = 0.f, ss1 = 0.f;
#pragma unroll
    for (int nt = 0; nt < 8; ++nt) {
        ss0 += acc[nt][0] * acc[nt][0] + acc[nt][1] * acc[nt][1];
        ss1 += acc[nt][2] * acc[nt][2] + acc[nt][3] * acc[nt][3];
    }
    ss0 += __shfl_xor_sync(0xffffffffu, ss0, 1, 4);
    ss0 += __shfl_xor_sync(0xffffffffu, ss0, 2, 4);
    ss1 += __shfl_xor_sync(0xffffffffu, ss1, 1, 4);
    ss1 += __shfl_xor_sync(0xffffffffu, ss1, 2, 4);

    const float qs = (type == 0) ? sf[h] * 1.44269504088896340736f : 1.0f;
    const float s0 = qs / fmaxf(sqrtf(ss0), 1e-12f);
    const float s1 = qs / fmaxf(sqrtf(ss1), 1e-12f);

    const int rg = row0 + warp * 16 + r;
    if (type < 2) {
        __nv_bfloat16* dh = (type == 0 ? g_Qh : g_Kh) + (size_t)h * T_TOT * 64;
        __nv_bfloat16* dl = (type == 0 ? g_Ql : g_Kl) + (size_t)h * T_TOT * 64;
#pragma unroll
        for (int nt = 0; nt < 8; ++nt) {
            float v0 = acc[nt][0] * s0, v1 = acc[nt][1] * s0;
            float v2 = acc[nt][2] * s1, v3 = acc[nt][3] * s1;
            uint32_t h0 = pack_bf16x2(v0, v1);
            uint32_t h1 = pack_bf16x2(v2, v3);
            uint32_t l0p = pack_bf16x2(v0 - __uint_as_float(h0 << 16),
                                       v1 - __uint_as_float(h0 & 0xffff0000u));
            uint32_t l1p = pack_bf16x2(v2 - __uint_as_float(h1 << 16),
                                       v3 - __uint_as_float(h1 & 0xffff0000u));
            size_t o0 = (size_t)(rg    ) * 64 + nt * 8 + q * 2;
            size_t o1 = (size_t)(rg + 8) * 64 + nt * 8 + q * 2;
            *(uint32_t*)&dh[o0] = h0; *(uint32_t*)&dl[o0] = l0p;
            *(uint32_t*)&dh[o1] = h1; *(uint32_t*)&dl[o1] = l1p;
        }
    } else {
        __nv_bfloat16* dh = g_VTh + (size_t)h * 64 * T_TOT;
        __nv_bfloat16* dl = g_VTl + (size_t)h * 64 * T_TOT;
#pragma unroll
        for (int nt = 0; nt < 8; ++nt) {
            float vv[4] = {acc[nt][0] * s0, acc[nt][1] * s0,
                           acc[nt][2] * s1, acc[nt][3] * s1};
#pragma unroll
            for (int e = 0; e < 4; ++e) {
                int col = nt * 8 + q * 2 + (e & 1);
                int row = rg + (e >> 1) * 8;
                __nv_bfloat16 hi, lo;
                split_bf16(vv[e], hi, lo);
                dh[(size_t)col * T_TOT + row] = hi;
                dl[(size_t)col * T_TOT + row] = lo;
            }
        }
    }
}

// ============================ attention (mma.sync bf16) ====================
// 256 threads = 8 warps; warp w owns q-rows [w*16, w*16+16). kv tile 64.
// smem per stage: Kh,Kl,VTh,VTl each [64][72] bf16 (pad 72 -> conflict-free
// B-frag LDS). Double buffered.  S regs -> P (bf16 hi/lo) -> PV, all in regs.
#define ROWPAD 72
#define ARR_SZ (64 * ROWPAD)            // ushorts per array
#define STAGE_SZ (4 * ARR_SZ)           // ushorts per stage
#define ATTN_SMEM (2 * STAGE_SZ * 2)    // bytes

__global__ __launch_bounds__(256, 1) void attn_kernel(float* __restrict__ out)
{
    extern __shared__ __nv_bfloat16 smb[];
    const int h  = blockIdx.y;
    const int it = 17 - (int)blockIdx.x;
    const int rb = it * 128;
    const int tid = threadIdx.x;
    const int warp = tid >> 5, lane = tid & 31;
    const int g = lane >> 2, q = lane & 3;
    const int row0 = warp * 16;
    const int rg0 = rb + row0 + g;       // global q row (and rg0+8)

    // ---- Q fragments (registers, whole kernel) ----
    uint32_t qh[4][4], ql[4][4];
    {
        const __nv_bfloat16* Qh = g_Qh + ((size_t)h * T_TOT + rg0) * 64;
        const __nv_bfloat16* Ql = g_Ql + ((size_t)h * T_TOT + rg0) * 64;
#pragma unroll
        for (int s = 0; s < 4; ++s) {
            int k = s * 16 + q * 2;
            qh[s][0] = *(const uint32_t*)&Qh[k];
            qh[s][1] = *(const uint32_t*)&Qh[8 * 64 + k];
            qh[s][2] = *(const uint32_t*)&Qh[k + 8];
            qh[s][3] = *(const uint32_t*)&Qh[8 * 64 + k + 8];
            ql[s][0] = *(const uint32_t*)&Ql[k];
            ql[s][1] = *(const uint32_t*)&Ql[8 * 64 + k];
            ql[s][2] = *(const uint32_t*)&Ql[k + 8];
            ql[s][3] = *(const uint32_t*)&Ql[8 * 64 + k + 8];
        }
    }

    float o[8][4];
#pragma unroll
    for (int j = 0; j < 8; ++j)
#pragma unroll
        for (int e = 0; e < 4; ++e) o[j][e] = 0.f;
    float l0 = 0.f, l1 = 0.f;

    const int jt0 = (it == 17) ? 2 : 0;
    const int jt1 = 2 * it + 1;

    // prefetch slot mapping: 8 uint4 per thread covering 4 arrays x 64x64 bf16
    const int pf_arr[8] = { (tid + 0*256) >> 9, (tid + 1*256) >> 9,
                            (tid + 2*256) >> 9, (tid + 3*256) >> 9,
                            (tid + 4*256) >> 9, (tid + 5*256) >> 9,
                            (tid + 6*256) >> 9, (tid + 7*256) >> 9 };
    const __nv_bfloat16* srcK[2] = { g_Kh + (size_t)h * T_TOT * 64,
                                     g_Kl + (size_t)h * T_TOT * 64 };
    const __nv_bfloat16* srcV[2] = { g_VTh + (size_t)h * 64 * T_TOT,
                                     g_VTl + (size_t)h * 64 * T_TOT };

    uint4 pf[8];
    auto fetch = [&](int jt) {
        const int cb = jt * 64;
#pragma unroll
        for (int i = 0; i < 8; ++i) {
            int slot = tid + i * 256;
            int arr = slot >> 9, s = slot & 511;
            int r = s >> 3, c = s & 7;
            const __nv_bfloat16* p;
            if (arr < 2) p = srcK[arr] + (size_t)(cb + r) * 64 + c * 8;
            else         p = srcV[arr - 2] + (size_t)r * T_TOT + cb + c * 8;
            pf[i] = *(const uint4*)p;
        }
    };
    fetch(jt0);

    for (int jt = jt0; jt <= jt1; ++jt) {
        const int cb = jt * 64;
        const int stage = (jt - jt0) & 1;
        __nv_bfloat16* st = smb + stage * STAGE_SZ;

        __syncthreads();   // stage reads from 2 iterations ago complete
#pragma unroll
        for (int i = 0; i < 8; ++i) {
            int slot = tid + i * 256;
            int arr = slot >> 9, s = slot & 511;
            int r = s >> 3, c = s & 7;
            *(uint4*)&st[arr * ARR_SZ + r * ROWPAD + c * 8] = pf[i];
        }
        if (jt < jt1) fetch(jt + 1);
        __syncthreads();

        const __nv_bfloat16* Khs  = st;
        const __nv_bfloat16* Kls  = st + ARR_SZ;
        const __nv_bfloat16* VThs = st + 2 * ARR_SZ;
        const __nv_bfloat16* VTls = st + 3 * ARR_SZ;

        // ---- S = Q K^T ----
        float sacc[8][4];
#pragma unroll
        for (int j = 0; j < 8; ++j)
#pragma unroll
            for (int e = 0; e < 4; ++e) sacc[j][e] = 0.f;

#pragma unroll
        for (int s = 0; s < 4; ++s) {
            const int kb = s * 16 + q * 2;
#pragma unroll
            for (int j = 0; j < 8; ++j) {
                const int n = j * 8 + g;
                uint32_t bh0 = *(const uint32_t*)&Khs[n * ROWPAD + kb];
                uint32_t bh1 = *(const uint32_t*)&Khs[n * ROWPAD + kb + 8];
                uint32_t bl0 = *(const uint32_t*)&Kls[n * ROWPAD + kb];
                uint32_t bl1 = *(const uint32_t*)&Kls[n * ROWPAD + kb + 8];
                mma16816(sacc[j], qh[s], bh0, bh1);
                mma16816(sacc[j], qh[s], bl0, bl1);
                mma16816(sacc[j], ql[s], bh0, bh1);
            }
        }

        // ---- mask + exp + pack P(hi/lo) ----
        const bool needMask = (jt >= 2 * it);
        uint32_t ph[8][2], pl[8][2];
#pragma unroll
        for (int j = 0; j < 8; ++j) {
            float e0 = sacc[j][0], e1 = sacc[j][1];
            float e2 = sacc[j][2], e3 = sacc[j][3];
            if (needMask) {
                int c0 = cb + j * 8 + q * 2, c1 = c0 + 1;
                if (c0 > rg0) e0 = -1e30f;
                if (c1 > rg0) e1 = -1e30f;
                if (c0 > rg0 + 8) e2 = -1e30f;
                if (c1 > rg0 + 8) e3 = -1e30f;
            }
            float p0 = ex2f_fast(e0), p1 = ex2f_fast(e1);
            float p2 = ex2f_fast(e2), p3 = ex2f_fast(e3);
            l0 += p0 + p1;
            l1 += p2 + p3;
            uint32_t h0 = pack_bf16x2(p0, p1);
            uint32_t h1 = pack_bf16x2(p2, p3);
            ph[j][0] = h0;
            ph[j][1] = h1;
            pl[j][0] = pack_bf16x2(p0 - __uint_as_float(h0 << 16),
                                   p1 - __uint_as_float(h0 & 0xffff0000u));
            pl[j][1] = pack_bf16x2(p2 - __uint_as_float(h1 << 16),
                                   p3 - __uint_as_float(h1 & 0xffff0000u));
        }

        // ---- O += P V ----
#pragma unroll
        for (int s = 0; s < 4; ++s) {
            uint32_t ah2[4] = { ph[2 * s][0], ph[2 * s][1],
                                ph[2 * s + 1][0], ph[2 * s + 1][1] };
            uint32_t al2[4] = { pl[2 * s][0], pl[2 * s][1],
                                pl[2 * s + 1][0], pl[2 * s + 1][1] };
            const int kb = s * 16 + q * 2;
#pragma unroll
            for (int j = 0; j < 8; ++j) {
                const int n = j * 8 + g;
                uint32_t bh0 = *(const uint32_t*)&VThs[n * ROWPAD + kb];
                uint32_t bh1 = *(const uint32_t*)&VThs[n * ROWPAD + kb + 8];
                uint32_t bl0 = *(const uint32_t*)&VTls[n * ROWPAD + kb];
                uint32_t bl1 = *(const uint32_t*)&VTls[n * ROWPAD + kb + 8];
                mma16816(o[j], ah2, bh0, bh1);
                mma16816(o[j], ah2, bl0, bl1);
                mma16816(o[j], al2, bh0, bh1);
            }
        }
    }

    // ---- reduce l over q-lanes, normalize, store ----
    l0 += __shfl_xor_sync(0xffffffffu, l0, 1, 4);
    l0 += __shfl_xor_sync(0xffffffffu, l0, 2, 4);
    l1 += __shfl_xor_sync(0xffffffffu, l1, 1, 4);
    l1 += __shfl_xor_sync(0xffffffffu, l1, 2, 4);
    const float inv0 = 1.0f / l0, inv1 = 1.0f / l1;

    float* og = out + ((size_t)h * T_TOT + rg0) * 64;
#pragma unroll
    for (int j = 0; j < 8; ++j) {
        int c = j * 8 + q * 2;
        *(float2*)(og + c)          = make_float2(o[j][0] * inv0, o[j][1] * inv0);
        *(float2*)(og + 8 * 64 + c) = make_float2(o[j][2] * inv1, o[j][3] * inv1);
    }
}

// ---------------------------------------------------------------------------
extern "C" void kernel_launch(void* const* d_in, const int* in_sizes, int n_in,
                              void* d_out, int out_size)
{
    (void)in_sizes; (void)n_in; (void)out_size;
    const float* x   = (const float*)d_in[0];
    const float* Wq  = (const float*)d_in[1];
    const float* Wk  = (const float*)d_in[2];
    const float* Wv  = (const float*)d_in[3];
    const float* Wqs = (const float*)d_in[4];
    const float* Wks = (const float*)d_in[5];
    const float* Wvs = (const float*)d_in[6];
    const float* sf  = (const float*)d_in[7];
    float* out = (float*)d_out;

    cudaFuncSetAttribute(proj_kernel,
                         cudaFuncAttributeMaxDynamicSharedMemorySize, PROJ_SMEM);
    cudaFuncSetAttribute(attn_kernel,
                         cudaFuncAttributeMaxDynamicSharedMemorySize, ATTN_SMEM);

    xconv_kernel<<<2304, 256>>>(x);
    wconv_kernel<<<dim3(16, 96), 256>>>(Wq, Wk, Wv, Wqs, Wks, Wvs);
    proj_kernel<<<dim3(48, 18), 256, PROJ_SMEM>>>(sf);
    attn_kernel<<<dim3(18, 16), 256, ATTN_SMEM>>>(out);
}

// round 5
// speedup vs baseline: 2.7749x; 1.0799x over previous
#include <cuda_runtime.h>
#include <cuda_bf16.h>
#include <math.h>
#include <cstdint>

// ---------------------------------------------------------------------------
// StatefulCausalAttention  (B=1, H=16, T=2304=128+2048+128, D=1024, dk=dv=64)
// R5: projection rewritten: tf32 mma.m16n8k8 single-term, fragment-shuffled
//     operands (prep kernels emit exact mma-frag order), q/k/v fused per block
//     (warp tile m64 x n48). Attention unchanged from R4 (bf16 hi/lo 3-term).
// ---------------------------------------------------------------------------

#define T_TOT 2304
#define D_IN  1024
#define NH    16

// projection outputs, bf16 hi/lo split (attention inputs)
__device__ __nv_bfloat16 g_Qh[NH * T_TOT * 64];
__device__ __nv_bfloat16 g_Ql[NH * T_TOT * 64];
__device__ __nv_bfloat16 g_Kh[NH * T_TOT * 64];
__device__ __nv_bfloat16 g_Kl[NH * T_TOT * 64];
__device__ __nv_bfloat16 g_VTh[NH * 64 * T_TOT];   // [h][dv][t]
__device__ __nv_bfloat16 g_VTl[NH * 64 * T_TOT];

// frag-shuffled tf32 operands
// g_Xf: [strip 144][chunk 64][t 2][lane 32][4]  (strip = row/16, chunk = k/16)
__device__ float g_Xf[144 * 64 * 2 * 32 * 4];
// g_Wf: [mat 6][h 16][chunk 64][ntl 8][lane 32][4]
__device__ float g_Wf[6 * 16 * 64 * 8 * 32 * 4];

// ============================ helpers ======================================
__device__ __forceinline__ float ex2f_fast(float x) {
    float y; asm("ex2.approx.f32 %0, %1;" : "=f"(y) : "f"(x)); return y;
}
__device__ __forceinline__ void mma16816(float* c, const uint32_t* a,
                                         uint32_t b0, uint32_t b1) {
    asm("mma.sync.aligned.m16n8k16.row.col.f32.bf16.bf16.f32 "
        "{%0,%1,%2,%3}, {%4,%5,%6,%7}, {%8,%9}, {%0,%1,%2,%3};"
        : "+f"(c[0]), "+f"(c[1]), "+f"(c[2]), "+f"(c[3])
        : "r"(a[0]), "r"(a[1]), "r"(a[2]), "r"(a[3]), "r"(b0), "r"(b1));
}
__device__ __forceinline__ void mma1688t(float* c, uint32_t a0, uint32_t a1,
                                         uint32_t a2, uint32_t a3,
                                         uint32_t b0, uint32_t b1) {
    asm("mma.sync.aligned.m16n8k8.row.col.f32.tf32.tf32.f32 "
        "{%0,%1,%2,%3}, {%4,%5,%6,%7}, {%8,%9}, {%0,%1,%2,%3};"
        : "+f"(c[0]), "+f"(c[1]), "+f"(c[2]), "+f"(c[3])
        : "r"(a0), "r"(a1), "r"(a2), "r"(a3), "r"(b0), "r"(b1));
}
__device__ __forceinline__ uint32_t to_tf32(float f) {
    uint32_t u; asm("cvt.rna.tf32.f32 %0, %1;" : "=r"(u) : "f"(f)); return u;
}
__device__ __forceinline__ uint32_t pack_bf16x2(float lo, float hi) {
    uint32_t r;
    asm("cvt.rn.bf16x2.f32 %0, %1, %2;" : "=r"(r) : "f"(hi), "f"(lo));
    return r;
}
__device__ __forceinline__ void split_bf16(float f, __nv_bfloat16& hi, __nv_bfloat16& lo) {
    hi = __float2bfloat16(f);
    lo = __float2bfloat16(f - __bfloat162float(hi));
}

// ============================ prep: X -> frag order ========================
// thread writes one uint4 = {X[r][k0+q], X[r][k0+8+q], X[r][k0+4+q], X[r][k0+12+q]}
__global__ __launch_bounds__(256) void xconv_kernel(const float* __restrict__ x)
{
    const int strip = blockIdx.x;          // 0..143
    for (int i = threadIdx.x; i < 4096; i += 256) {
        int c = i >> 6, rest = i & 63;
        int t = rest >> 5, ln = rest & 31;
        int g = ln >> 2, q = ln & 3;
        const float* xr = x + (size_t)(strip * 16 + t * 8 + g) * D_IN + c * 16;
        uint4 v;
        v.x = to_tf32(xr[q]);
        v.y = to_tf32(xr[8 + q]);
        v.z = to_tf32(xr[4 + q]);
        v.w = to_tf32(xr[12 + q]);
        ((uint4*)g_Xf)[(size_t)(strip * 64 + c) * 64 + rest] = v;
    }
}

// ============================ prep: W -> frag order ========================
// block = (chunk c, mat*16+h); thread = (ntl = tid>>5, lane)
// uint4 = {W[k0+r][n], W[k0+8+r][n], W[k0+4+r][n], W[k0+12+r][n]}
__global__ __launch_bounds__(256) void wconv_kernel(
    const float* __restrict__ Wq,  const float* __restrict__ Wk,  const float* __restrict__ Wv,
    const float* __restrict__ Wqs, const float* __restrict__ Wks, const float* __restrict__ Wvs)
{
    const int c  = blockIdx.x;             // 0..63
    const int mh = blockIdx.y;             // 0..95
    const int mat = mh >> 4, h = mh & 15;
    const float* W;
    switch (mat) {
        case 0: W = Wq;  break; case 1: W = Wqs; break;
        case 2: W = Wk;  break; case 3: W = Wks; break;
        case 4: W = Wv;  break; default: W = Wvs; break;
    }
    W += (size_t)h * D_IN * 64;
    const int tid = threadIdx.x;
    const int ntl = tid >> 5, ln = tid & 31;
    const int g = ln >> 2, r = ln & 3;
    const int n = ntl * 8 + g, k0 = c * 16;
    uint4 v;
    v.x = to_tf32(W[(size_t)(k0 + r) * 64 + n]);
    v.y = to_tf32(W[(size_t)(k0 + 8 + r) * 64 + n]);
    v.z = to_tf32(W[(size_t)(k0 + 4 + r) * 64 + n]);
    v.w = to_tf32(W[(size_t)(k0 + 12 + r) * 64 + n]);
    ((uint4*)g_Wf)[((size_t)(mat * 16 + h) * 64 + c) * 256 + tid] = v;
}

// ============================ projection (tf32 mma) ========================
// block (h, by): rows by*128..+127, all of q,k,v (N=192). 8 warps:
// mi = warp>>2 (m64 = 4 strips), ni = warp&3 (n48 = 6 nt of 8).
// k chunks of 16 (2 ksteps), double-buffered frag-order smem.
// smem: stage s at s*20480: A 512 uint4 (8KB), B 768 uint4 (12KB);
//       norm[3][128] floats at 40960.
#define PROJ_SMEM (40960 + 1536)

__global__ __launch_bounds__(256, 1) void proj_kernel(const float* __restrict__ sf)
{
    extern __shared__ char smc[];
    float* nrm = (float*)(smc + 40960);
    const int h  = blockIdx.x;
    const int by = blockIdx.y;
    const int state = (by == 0 || by == 17) ? 1 : 0;
    const int tid = threadIdx.x, warp = tid >> 5, lane = tid & 31;
    const int mi = warp >> 2, ni = warp & 3;
    const int g = lane >> 2, qq = lane & 3;
    const int strip0 = by * 8;

    for (int i = tid; i < 384; i += 256) nrm[i] = 0.f;

    const uint4* Xfu = (const uint4*)g_Xf;
    const uint4* Wfu = (const uint4*)g_Wf;

    float acc[4][6][4];
#pragma unroll
    for (int st = 0; st < 4; ++st)
#pragma unroll
        for (int nt = 0; nt < 6; ++nt)
#pragma unroll
            for (int e = 0; e < 4; ++e) acc[st][nt][e] = 0.f;

    uint4 pv[5];
    auto fetch = [&](int c) {
#pragma unroll
        for (int i = 0; i < 5; ++i) {
            int slot = tid + i * 256;
            if (slot < 512) {
                pv[i] = Xfu[(size_t)((strip0 + (slot >> 6)) * 64 + c) * 64 + (slot & 63)];
            } else {
                int s2 = slot - 512;
                int mat = (s2 >> 8) * 2 + state;
                pv[i] = Wfu[((size_t)(mat * 16 + h) * 64 + c) * 256 + (s2 & 255)];
            }
        }
    };

    fetch(0);
    for (int c = 0; c < 64; ++c) {
        char* sa = smc + (c & 1) * 20480;
#pragma unroll
        for (int i = 0; i < 5; ++i) {
            int slot = tid + i * 256;
            if (slot < 512) *(uint4*)(sa + slot * 16) = pv[i];
            else            *(uint4*)(sa + 8192 + (slot - 512) * 16) = pv[i];
        }
        if (c + 1 < 64) fetch(c + 1);
        __syncthreads();

        uint4 Af[4][2], Bf[6];
#pragma unroll
        for (int st = 0; st < 4; ++st) {
#pragma unroll
            for (int t = 0; t < 2; ++t)
                Af[st][t] = *(const uint4*)(sa + (((mi * 4 + st) * 2 + t) * 32 + lane) * 16);
        }
#pragma unroll
        for (int nt = 0; nt < 6; ++nt)
            Bf[nt] = *(const uint4*)(sa + 8192 + ((ni * 6 + nt) * 32 + lane) * 16);

#pragma unroll
        for (int s = 0; s < 2; ++s) {
#pragma unroll
            for (int st = 0; st < 4; ++st) {
                uint32_t a0 = s ? Af[st][0].y : Af[st][0].x;
                uint32_t a1 = s ? Af[st][1].y : Af[st][1].x;
                uint32_t a2 = s ? Af[st][0].w : Af[st][0].z;
                uint32_t a3 = s ? Af[st][1].w : Af[st][1].z;
#pragma unroll
                for (int nt = 0; nt < 6; ++nt) {
                    uint32_t b0 = s ? Bf[nt].y : Bf[nt].x;
                    uint32_t b1 = s ? Bf[nt].w : Bf[nt].z;
                    mma1688t(acc[st][nt], a0, a1, a2, a3, b0, b1);
                }
            }
        }
        __syncthreads();
    }

    // ---- norm partials (smem atomics; rows x mats = 128 x 3) ----
#pragma unroll
    for (int st = 0; st < 4; ++st) {
#pragma unroll
        for (int nt = 0; nt < 6; ++nt) {
            int mat = (ni * 6 + nt) >> 3;
            int rl0 = (mi * 4 + st) * 16 + g;
            atomicAdd(&nrm[mat * 128 + rl0],
                      acc[st][nt][0] * acc[st][nt][0] + acc[st][nt][1] * acc[st][nt][1]);
            atomicAdd(&nrm[mat * 128 + rl0 + 8],
                      acc[st][nt][2] * acc[st][nt][2] + acc[st][nt][3] * acc[st][nt][3]);
        }
    }
    __syncthreads();

    // ---- scale + store (bf16 hi/lo; V transposed) ----
    const float qs = sf[h] * 1.44269504088896340736f;
#pragma unroll
    for (int st = 0; st < 4; ++st) {
        const int rl0 = (mi * 4 + st) * 16 + g;
        const int rg0 = by * 128 + rl0;
#pragma unroll
        for (int nt = 0; nt < 6; ++nt) {
            const int ntg = ni * 6 + nt;
            const int mat = ntg >> 3;
            const int ntl = ntg & 7;
            const float mult = (mat == 0) ? qs : 1.0f;
            float inv0 = mult / fmaxf(sqrtf(nrm[mat * 128 + rl0]),     1e-12f);
            float inv1 = mult / fmaxf(sqrtf(nrm[mat * 128 + rl0 + 8]), 1e-12f);
            float v0 = acc[st][nt][0] * inv0, v1 = acc[st][nt][1] * inv0;
            float v2 = acc[st][nt][2] * inv1, v3 = acc[st][nt][3] * inv1;
            const int col = ntl * 8 + qq * 2;
            if (mat < 2) {
                __nv_bfloat16* dh = (mat == 0 ? g_Qh : g_Kh) + (size_t)h * T_TOT * 64;
                __nv_bfloat16* dl = (mat == 0 ? g_Ql : g_Kl) + (size_t)h * T_TOT * 64;
                uint32_t h0 = pack_bf16x2(v0, v1);
                uint32_t h1 = pack_bf16x2(v2, v3);
                uint32_t l0p = pack_bf16x2(v0 - __uint_as_float(h0 << 16),
                                           v1 - __uint_as_float(h0 & 0xffff0000u));
                uint32_t l1p = pack_bf16x2(v2 - __uint_as_float(h1 << 16),
                                           v3 - __uint_as_float(h1 & 0xffff0000u));
                size_t o0 = (size_t)(rg0    ) * 64 + col;
                size_t o1 = (size_t)(rg0 + 8) * 64 + col;
                *(uint32_t*)&dh[o0] = h0; *(uint32_t*)&dl[o0] = l0p;
                *(uint32_t*)&dh[o1] = h1; *(uint32_t*)&dl[o1] = l1p;
            } else {
                __nv_bfloat16* dh = g_VTh + (size_t)h * 64 * T_TOT;
                __nv_bfloat16* dl = g_VTl + (size_t)h * 64 * T_TOT;
                float vv[4] = {v0, v1, v2, v3};
#pragma unroll
                for (int e = 0; e < 4; ++e) {
                    int cc = col + (e & 1);
                    int rr = rg0 + (e >> 1) * 8;
                    __nv_bfloat16 hi, lo;
                    split_bf16(vv[e], hi, lo);
                    dh[(size_t)cc * T_TOT + rr] = hi;
                    dl[(size_t)cc * T_TOT + rr] = lo;
                }
            }
        }
    }
}

// ============================ attention (unchanged R4) =====================
#define ROWPAD 72
#define ARR_SZ (64 * ROWPAD)
#define STAGE_SZ (4 * ARR_SZ)
#define ATTN_SMEM (2 * STAGE_SZ * 2)

__global__ __launch_bounds__(256, 1) void attn_kernel(float* __restrict__ out)
{
    extern __shared__ __nv_bfloat16 smb[];
    const int h  = blockIdx.y;
    const int it = 17 - (int)blockIdx.x;
    const int rb = it * 128;
    const int tid = threadIdx.x;
    const int warp = tid >> 5, lane = tid & 31;
    const int g = lane >> 2, q = lane & 3;
    const int row0 = warp * 16;
    const int rg0 = rb + row0 + g;

    uint32_t qh[4][4], ql[4][4];
    {
        const __nv_bfloat16* Qh = g_Qh + ((size_t)h * T_TOT + rg0) * 64;
        const __nv_bfloat16* Ql = g_Ql + ((size_t)h * T_TOT + rg0) * 64;
#pragma unroll
        for (int s = 0; s < 4; ++s) {
            int k = s * 16 + q * 2;
            qh[s][0] = *(const uint32_t*)&Qh[k];
            qh[s][1] = *(const uint32_t*)&Qh[8 * 64 + k];
            qh[s][2] = *(const uint32_t*)&Qh[k + 8];
            qh[s][3] = *(const uint32_t*)&Qh[8 * 64 + k + 8];
            ql[s][0] = *(const uint32_t*)&Ql[k];
            ql[s][1] = *(const uint32_t*)&Ql[8 * 64 + k];
            ql[s][2] = *(const uint32_t*)&Ql[k + 8];
            ql[s][3] = *(const uint32_t*)&Ql[8 * 64 + k + 8];
        }
    }

    float o[8][4];
#pragma unroll
    for (int j = 0; j < 8; ++j)
#pragma unroll
        for (int e = 0; e < 4; ++e) o[j][e] = 0.f;
    float l0 = 0.f, l1 = 0.f;

    const int jt0 = (it == 17) ? 2 : 0;
    const int jt1 = 2 * it + 1;

    const __nv_bfloat16* srcK[2] = { g_Kh + (size_t)h * T_TOT * 64,
                                     g_Kl + (size_t)h * T_TOT * 64 };
    const __nv_bfloat16* srcV[2] = { g_VTh + (size_t)h * 64 * T_TOT,
                                     g_VTl + (size_t)h * 64 * T_TOT };

    uint4 pf[8];
    auto fetch = [&](int jt) {
        const int cb = jt * 64;
#pragma unroll
        for (int i = 0; i < 8; ++i) {
            int slot = tid + i * 256;
            int arr = slot >> 9, s = slot & 511;
            int r = s >> 3, c = s & 7;
            const __nv_bfloat16* p;
            if (arr < 2) p = srcK[arr] + (size_t)(cb + r) * 64 + c * 8;
            else         p = srcV[arr - 2] + (size_t)r * T_TOT + cb + c * 8;
            pf[i] = *(const uint4*)p;
        }
    };
    fetch(jt0);

    for (int jt = jt0; jt <= jt1; ++jt) {
        const int cb = jt * 64;
        const int stage = (jt - jt0) & 1;
        __nv_bfloat16* st = smb + stage * STAGE_SZ;

        __syncthreads();
#pragma unroll
        for (int i = 0; i < 8; ++i) {
            int slot = tid + i * 256;
            int arr = slot >> 9, s = slot & 511;
            int r = s >> 3, c = s & 7;
            *(uint4*)&st[arr * ARR_SZ + r * ROWPAD + c * 8] = pf[i];
        }
        if (jt < jt1) fetch(jt + 1);
        __syncthreads();

        const __nv_bfloat16* Khs  = st;
        const __nv_bfloat16* Kls  = st + ARR_SZ;
        const __nv_bfloat16* VThs = st + 2 * ARR_SZ;
        const __nv_bfloat16* VTls = st + 3 * ARR_SZ;

        float sacc[8][4];
#pragma unroll
        for (int j = 0; j < 8; ++j)
#pragma unroll
            for (int e = 0; e < 4; ++e) sacc[j][e] = 0.f;

#pragma unroll
        for (int s = 0; s < 4; ++s) {
            const int kb = s * 16 + q * 2;
#pragma unroll
            for (int j = 0; j < 8; ++j) {
                const int n = j * 8 + g;
                uint32_t bh0 = *(const uint32_t*)&Khs[n * ROWPAD + kb];
                uint32_t bh1 = *(const uint32_t*)&Khs[n * ROWPAD + kb + 8];
                uint32_t bl0 = *(const uint32_t*)&Kls[n * ROWPAD + kb];
                uint32_t bl1 = *(const uint32_t*)&Kls[n * ROWPAD + kb + 8];
                mma16816(sacc[j], qh[s], bh0, bh1);
                mma16816(sacc[j], qh[s], bl0, bl1);
                mma16816(sacc[j], ql[s], bh0, bh1);
            }
        }

        const bool needMask = (jt >= 2 * it);
        uint32_t ph[8][2], pl[8][2];
#pragma unroll
        for (int j = 0; j < 8; ++j) {
            float e0 = sacc[j][0], e1 = sacc[j][1];
            float e2 = sacc[j][2], e3 = sacc[j][3];
            if (needMask) {
                int c0 = cb + j * 8 + q * 2, c1 = c0 + 1;
                if (c0 > rg0) e0 = -1e30f;
                if (c1 > rg0) e1 = -1e30f;
                if (c0 > rg0 + 8) e2 = -1e30f;
                if (c1 > rg0 + 8) e3 = -1e30f;
            }
            float p0 = ex2f_fast(e0), p1 = ex2f_fast(e1);
            float p2 = ex2f_fast(e2), p3 = ex2f_fast(e3);
            l0 += p0 + p1;
            l1 += p2 + p3;
            uint32_t h0 = pack_bf16x2(p0, p1);
            uint32_t h1 = pack_bf16x2(p2, p3);
            ph[j][0] = h0;
            ph[j][1] = h1;
            pl[j][0] = pack_bf16x2(p0 - __uint_as_float(h0 << 16),
                                   p1 - __uint_as_float(h0 & 0xffff0000u));
            pl[j][1] = pack_bf16x2(p2 - __uint_as_float(h1 << 16),
                                   p3 - __uint_as_float(h1 & 0xffff0000u));
        }

#pragma unroll
        for (int s = 0; s < 4; ++s) {
            uint32_t ah2[4] = { ph[2 * s][0], ph[2 * s][1],
                                ph[2 * s + 1][0], ph[2 * s + 1][1] };
            uint32_t al2[4] = { pl[2 * s][0], pl[2 * s][1],
                                pl[2 * s + 1][0], pl[2 * s + 1][1] };
            const int kb = s * 16 + q * 2;
#pragma unroll
            for (int j = 0; j < 8; ++j) {
                const int n = j * 8 + g;
                uint32_t bh0 = *(const uint32_t*)&VThs[n * ROWPAD + kb];
                uint32_t bh1 = *(const uint32_t*)&VThs[n * ROWPAD + kb + 8];
                uint32_t bl0 = *(const uint32_t*)&VTls[n * ROWPAD + kb];
                uint32_t bl1 = *(const uint32_t*)&VTls[n * ROWPAD + kb + 8];
                mma16816(o[j], ah2, bh0, bh1);
                mma16816(o[j], ah2, bl0, bl1);
                mma16816(o[j], al2, bh0, bh1);
            }
        }
    }

    l0 += __shfl_xor_sync(0xffffffffu, l0, 1, 4);
    l0 += __shfl_xor_sync(0xffffffffu, l0, 2, 4);
    l1 += __shfl_xor_sync(0xffffffffu, l1, 1, 4);
    l1 += __shfl_xor_sync(0xffffffffu, l1, 2, 4);
    const float inv0 = 1.0f / l0, inv1 = 1.0f / l1;

    float* og = out + ((size_t)h * T_TOT + rg0) * 64;
#pragma unroll
    for (int j = 0; j < 8; ++j) {
        int c = j * 8 + q * 2;
        *(float2*)(og + c)          = make_float2(o[j][0] * inv0, o[j][1] * inv0);
        *(float2*)(og + 8 * 64 + c) = make_float2(o[j][2] * inv1, o[j][3] * inv1);
    }
}

// ---------------------------------------------------------------------------
extern "C" void kernel_launch(void* const* d_in, const int* in_sizes, int n_in,
                              void* d_out, int out_size)
{
    (void)in_sizes; (void)n_in; (void)out_size;
    const float* x   = (const float*)d_in[0];
    const float* Wq  = (const float*)d_in[1];
    const float* Wk  = (const float*)d_in[2];
    const float* Wv  = (const float*)d_in[3];
    const float* Wqs = (const float*)d_in[4];
    const float* Wks = (const float*)d_in[5];
    const float* Wvs = (const float*)d_in[6];
    const float* sf  = (const float*)d_in[7];
    float* out = (float*)d_out;

    cudaFuncSetAttribute(proj_kernel,
                         cudaFuncAttributeMaxDynamicSharedMemorySize, PROJ_SMEM);
    cudaFuncSetAttribute(attn_kernel,
                         cudaFuncAttributeMaxDynamicSharedMemorySize, ATTN_SMEM);

    xconv_kernel<<<144, 256>>>(x);
    wconv_kernel<<<dim3(64, 96), 256>>>(Wq, Wk, Wv, Wqs, Wks, Wvs);
    proj_kernel<<<dim3(16, 18), 256, PROJ_SMEM>>>(sf);
    attn_kernel<<<dim3(18, 16), 256, ATTN_SMEM>>>(out);
}

// round 6
// speedup vs baseline: 2.8512x; 1.0275x over previous
#include <cuda_runtime.h>
#include <cuda_bf16.h>
#include <math.h>
#include <cstdint>

// ---------------------------------------------------------------------------
// StatefulCausalAttention  (B=1, H=16, T=2304=128+2048+128, D=1024, dk=dv=64)
// R6: attention rewritten: tf32 single-term S-path (Q,K stored tf32 fp32),
//     bf16 hi/lo PV unchanged, cp.async double-buffered stages, 2 CTAs/SM.
//     Projection mainloop unchanged (tf32 frag); epilogue emits Q/K as tf32.
// ---------------------------------------------------------------------------

#define T_TOT 2304
#define D_IN  1024
#define NH    16

// projection outputs
__device__ float g_Qf[NH * T_TOT * 64];            // tf32-rounded, * sf * log2e
__device__ float g_Kf[NH * T_TOT * 64];            // tf32-rounded
__device__ __nv_bfloat16 g_VTh[NH * 64 * T_TOT];   // [h][dv][t]
__device__ __nv_bfloat16 g_VTl[NH * 64 * T_TOT];

// frag-shuffled tf32 operands for projection
__device__ float g_Xf[144 * 64 * 2 * 32 * 4];
__device__ float g_Wf[6 * 16 * 64 * 8 * 32 * 4];

// ============================ helpers ======================================
__device__ __forceinline__ float ex2f_fast(float x) {
    float y; asm("ex2.approx.f32 %0, %1;" : "=f"(y) : "f"(x)); return y;
}
__device__ __forceinline__ void mma16816(float* c, const uint32_t* a,
                                         uint32_t b0, uint32_t b1) {
    asm("mma.sync.aligned.m16n8k16.row.col.f32.bf16.bf16.f32 "
        "{%0,%1,%2,%3}, {%4,%5,%6,%7}, {%8,%9}, {%0,%1,%2,%3};"
        : "+f"(c[0]), "+f"(c[1]), "+f"(c[2]), "+f"(c[3])
        : "r"(a[0]), "r"(a[1]), "r"(a[2]), "r"(a[3]), "r"(b0), "r"(b1));
}
__device__ __forceinline__ void mma1688t(float* c, uint32_t a0, uint32_t a1,
                                         uint32_t a2, uint32_t a3,
                                         uint32_t b0, uint32_t b1) {
    asm("mma.sync.aligned.m16n8k8.row.col.f32.tf32.tf32.f32 "
        "{%0,%1,%2,%3}, {%4,%5,%6,%7}, {%8,%9}, {%0,%1,%2,%3};"
        : "+f"(c[0]), "+f"(c[1]), "+f"(c[2]), "+f"(c[3])
        : "r"(a0), "r"(a1), "r"(a2), "r"(a3), "r"(b0), "r"(b1));
}
__device__ __forceinline__ uint32_t to_tf32(float f) {
    uint32_t u; asm("cvt.rna.tf32.f32 %0, %1;" : "=r"(u) : "f"(f)); return u;
}
__device__ __forceinline__ uint32_t pack_bf16x2(float lo, float hi) {
    uint32_t r;
    asm("cvt.rn.bf16x2.f32 %0, %1, %2;" : "=r"(r) : "f"(hi), "f"(lo));
    return r;
}
__device__ __forceinline__ void split_bf16(float f, __nv_bfloat16& hi, __nv_bfloat16& lo) {
    hi = __float2bfloat16(f);
    lo = __float2bfloat16(f - __bfloat162float(hi));
}
__device__ __forceinline__ uint32_t smem_u32(const void* p) {
    uint32_t a;
    asm("{ .reg .u64 t; cvta.to.shared.u64 t, %1; cvt.u32.u64 %0, t; }" : "=r"(a) : "l"(p));
    return a;
}
#define CP_ASYNC16(dst, src) \
    asm volatile("cp.async.cg.shared.global [%0], [%1], 16;" :: "r"(dst), "l"(src))
#define CP_COMMIT() asm volatile("cp.async.commit_group;" ::: "memory")
#define CP_WAIT(n)  asm volatile("cp.async.wait_group %0;" :: "n"(n) : "memory")

// ============================ prep: X -> frag order ========================
__global__ __launch_bounds__(256) void xconv_kernel(const float* __restrict__ x)
{
    const int strip = blockIdx.x;          // 0..143
    for (int i = threadIdx.x; i < 4096; i += 256) {
        int c = i >> 6, rest = i & 63;
        int t = rest >> 5, ln = rest & 31;
        int g = ln >> 2, q = ln & 3;
        const float* xr = x + (size_t)(strip * 16 + t * 8 + g) * D_IN + c * 16;
        uint4 v;
        v.x = to_tf32(xr[q]);
        v.y = to_tf32(xr[8 + q]);
        v.z = to_tf32(xr[4 + q]);
        v.w = to_tf32(xr[12 + q]);
        ((uint4*)g_Xf)[(size_t)(strip * 64 + c) * 64 + rest] = v;
    }
}

// ============================ prep: W -> frag order ========================
__global__ __launch_bounds__(256) void wconv_kernel(
    const float* __restrict__ Wq,  const float* __restrict__ Wk,  const float* __restrict__ Wv,
    const float* __restrict__ Wqs, const float* __restrict__ Wks, const float* __restrict__ Wvs)
{
    const int cb = blockIdx.x * 16;        // 16 chunks per block
    const int mh = blockIdx.y;             // 0..95
    const int mat = mh >> 4, h = mh & 15;
    const float* W;
    switch (mat) {
        case 0: W = Wq;  break; case 1: W = Wqs; break;
        case 2: W = Wk;  break; case 3: W = Wks; break;
        case 4: W = Wv;  break; default: W = Wvs; break;
    }
    W += (size_t)h * D_IN * 64;
    const int tid = threadIdx.x;
    const int ntl = tid >> 5, ln = tid & 31;
    const int g = ln >> 2, r = ln & 3;
    const int n = ntl * 8 + g;
#pragma unroll 4
    for (int ci = 0; ci < 16; ++ci) {
        const int c = cb + ci, k0 = c * 16;
        uint4 v;
        v.x = to_tf32(W[(size_t)(k0 + r) * 64 + n]);
        v.y = to_tf32(W[(size_t)(k0 + 8 + r) * 64 + n]);
        v.z = to_tf32(W[(size_t)(k0 + 4 + r) * 64 + n]);
        v.w = to_tf32(W[(size_t)(k0 + 12 + r) * 64 + n]);
        ((uint4*)g_Wf)[((size_t)(mat * 16 + h) * 64 + c) * 256 + tid] = v;
    }
}

// ============================ projection (tf32 mma) ========================
#define PROJ_SMEM (40960 + 1536)

__global__ __launch_bounds__(256, 1) void proj_kernel(const float* __restrict__ sf)
{
    extern __shared__ char smc[];
    float* nrm = (float*)(smc + 40960);
    const int h  = blockIdx.x;
    const int by = blockIdx.y;
    const int state = (by == 0 || by == 17) ? 1 : 0;
    const int tid = threadIdx.x, warp = tid >> 5, lane = tid & 31;
    const int mi = warp >> 2, ni = warp & 3;
    const int g = lane >> 2, qq = lane & 3;
    const int strip0 = by * 8;

    for (int i = tid; i < 384; i += 256) nrm[i] = 0.f;

    const uint4* Xfu = (const uint4*)g_Xf;
    const uint4* Wfu = (const uint4*)g_Wf;

    float acc[4][6][4];
#pragma unroll
    for (int st = 0; st < 4; ++st)
#pragma unroll
        for (int nt = 0; nt < 6; ++nt)
#pragma unroll
            for (int e = 0; e < 4; ++e) acc[st][nt][e] = 0.f;

    uint4 pv[5];
    auto fetch = [&](int c) {
#pragma unroll
        for (int i = 0; i < 5; ++i) {
            int slot = tid + i * 256;
            if (slot < 512) {
                pv[i] = Xfu[(size_t)((strip0 + (slot >> 6)) * 64 + c) * 64 + (slot & 63)];
            } else {
                int s2 = slot - 512;
                int mat = (s2 >> 8) * 2 + state;
                pv[i] = Wfu[((size_t)(mat * 16 + h) * 64 + c) * 256 + (s2 & 255)];
            }
        }
    };

    fetch(0);
    for (int c = 0; c < 64; ++c) {
        char* sa = smc + (c & 1) * 20480;
#pragma unroll
        for (int i = 0; i < 5; ++i) {
            int slot = tid + i * 256;
            if (slot < 512) *(uint4*)(sa + slot * 16) = pv[i];
            else            *(uint4*)(sa + 8192 + (slot - 512) * 16) = pv[i];
        }
        if (c + 1 < 64) fetch(c + 1);
        __syncthreads();

        uint4 Af[4][2], Bf[6];
#pragma unroll
        for (int st = 0; st < 4; ++st) {
#pragma unroll
            for (int t = 0; t < 2; ++t)
                Af[st][t] = *(const uint4*)(sa + (((mi * 4 + st) * 2 + t) * 32 + lane) * 16);
        }
#pragma unroll
        for (int nt = 0; nt < 6; ++nt)
            Bf[nt] = *(const uint4*)(sa + 8192 + ((ni * 6 + nt) * 32 + lane) * 16);

#pragma unroll
        for (int s = 0; s < 2; ++s) {
#pragma unroll
            for (int st = 0; st < 4; ++st) {
                uint32_t a0 = s ? Af[st][0].y : Af[st][0].x;
                uint32_t a1 = s ? Af[st][1].y : Af[st][1].x;
                uint32_t a2 = s ? Af[st][0].w : Af[st][0].z;
                uint32_t a3 = s ? Af[st][1].w : Af[st][1].z;
#pragma unroll
                for (int nt = 0; nt < 6; ++nt) {
                    uint32_t b0 = s ? Bf[nt].y : Bf[nt].x;
                    uint32_t b1 = s ? Bf[nt].w : Bf[nt].z;
                    mma1688t(acc[st][nt], a0, a1, a2, a3, b0, b1);
                }
            }
        }
        __syncthreads();
    }

    // ---- norm partials ----
#pragma unroll
    for (int st = 0; st < 4; ++st) {
#pragma unroll
        for (int nt = 0; nt < 6; ++nt) {
            int mat = (ni * 6 + nt) >> 3;
            int rl0 = (mi * 4 + st) * 16 + g;
            atomicAdd(&nrm[mat * 128 + rl0],
                      acc[st][nt][0] * acc[st][nt][0] + acc[st][nt][1] * acc[st][nt][1]);
            atomicAdd(&nrm[mat * 128 + rl0 + 8],
                      acc[st][nt][2] * acc[st][nt][2] + acc[st][nt][3] * acc[st][nt][3]);
        }
    }
    __syncthreads();

    // ---- scale + store: Q/K as tf32 fp32; V transposed bf16 hi/lo ----
    const float qs = sf[h] * 1.44269504088896340736f;
#pragma unroll
    for (int st = 0; st < 4; ++st) {
        const int rl0 = (mi * 4 + st) * 16 + g;
        const int rg0 = by * 128 + rl0;
#pragma unroll
        for (int nt = 0; nt < 6; ++nt) {
            const int ntg = ni * 6 + nt;
            const int mat = ntg >> 3;
            const int ntl = ntg & 7;
            const float mult = (mat == 0) ? qs : 1.0f;
            float inv0 = mult / fmaxf(sqrtf(nrm[mat * 128 + rl0]),     1e-12f);
            float inv1 = mult / fmaxf(sqrtf(nrm[mat * 128 + rl0 + 8]), 1e-12f);
            float v0 = acc[st][nt][0] * inv0, v1 = acc[st][nt][1] * inv0;
            float v2 = acc[st][nt][2] * inv1, v3 = acc[st][nt][3] * inv1;
            const int col = ntl * 8 + qq * 2;
            if (mat < 2) {
                float* dst = (mat == 0 ? g_Qf : g_Kf) + (size_t)h * T_TOT * 64;
                uint2 w0 = make_uint2(to_tf32(v0), to_tf32(v1));
                uint2 w1 = make_uint2(to_tf32(v2), to_tf32(v3));
                *(uint2*)(dst + (size_t)(rg0    ) * 64 + col) = w0;
                *(uint2*)(dst + (size_t)(rg0 + 8) * 64 + col) = w1;
            } else {
                __nv_bfloat16* dh = g_VTh + (size_t)h * 64 * T_TOT;
                __nv_bfloat16* dl = g_VTl + (size_t)h * 64 * T_TOT;
                float vv[4] = {v0, v1, v2, v3};
#pragma unroll
                for (int e = 0; e < 4; ++e) {
                    int cc = col + (e & 1);
                    int rr = rg0 + (e >> 1) * 8;
                    __nv_bfloat16 hi, lo;
                    split_bf16(vv[e], hi, lo);
                    dh[(size_t)cc * T_TOT + rr] = hi;
                    dl[(size_t)cc * T_TOT + rr] = lo;
                }
            }
        }
    }
}

// ============================ attention v2 =================================
// 256 threads, 8 warps x 16 q-rows, kv-tile 64, 2 CTAs/SM.
// Stage layout (bytes, per stage of 35840):
//   K  fp32 [64][68]  @ 0       (row 272 B; B-frag LDS.32 conflict-free)
//   VTh bf16 [64][72] @ 17408
//   VTl bf16 [64][72] @ 26624
#define STAGE_B 35840
#define ATTN_SMEM (2 * STAGE_B)

__global__ __launch_bounds__(256, 2) void attn_kernel(float* __restrict__ out)
{
    extern __shared__ char smc[];
    const uint32_t sb = smem_u32(smc);
    const int h  = blockIdx.y;
    const int it = 17 - (int)blockIdx.x;
    const int rb = it * 128;
    const int tid = threadIdx.x;
    const int warp = tid >> 5, lane = tid & 31;
    const int g = lane >> 2, q = lane & 3;
    const int rg0 = rb + warp * 16 + g;

    // ---- Q fragments (tf32 fp32, registers) ----
    uint32_t qf[8][4];
    {
        const float* Qf = g_Qf + ((size_t)h * T_TOT + rg0) * 64;
#pragma unroll
        for (int ks = 0; ks < 8; ++ks) {
            int k = ks * 8 + q;
            qf[ks][0] = __float_as_uint(Qf[k]);
            qf[ks][1] = __float_as_uint(Qf[8 * 64 + k]);
            qf[ks][2] = __float_as_uint(Qf[k + 4]);
            qf[ks][3] = __float_as_uint(Qf[8 * 64 + k + 4]);
        }
    }

    float o[8][4];
#pragma unroll
    for (int j = 0; j < 8; ++j)
#pragma unroll
        for (int e = 0; e < 4; ++e) o[j][e] = 0.f;
    float l0 = 0.f, l1 = 0.f;

    const int jt0 = (it == 17) ? 2 : 0;
    const int jt1 = 2 * it + 1;

    auto issue_stage = [&](int jt, int buf) {
        const int cb = jt * 64;
        const uint32_t stb = sb + buf * STAGE_B;
#pragma unroll
        for (int i = 0; i < 8; ++i) {
            int slot = tid + i * 256;
            if (slot < 1024) {
                int row = slot >> 4, ch = slot & 15;
                const float* src = g_Kf + ((size_t)h * T_TOT + cb + row) * 64 + ch * 4;
                CP_ASYNC16(stb + row * 272 + ch * 16, src);
            } else {
                int s2 = slot - 1024;
                int arr = s2 >> 9, s3 = s2 & 511;
                int row = s3 >> 3, c = s3 & 7;
                const __nv_bfloat16* src = (arr ? g_VTl : g_VTh)
                    + (size_t)h * 64 * T_TOT + (size_t)row * T_TOT + cb + c * 8;
                CP_ASYNC16(stb + 17408 + arr * 9216 + row * 144 + c * 16, src);
            }
        }
    };

    issue_stage(jt0, 0);
    CP_COMMIT();

    for (int jt = jt0; jt <= jt1; ++jt) {
        const int cb = jt * 64;
        const int buf = (jt - jt0) & 1;
        const char* st = smc + buf * STAGE_B;

        if (jt < jt1) { issue_stage(jt + 1, buf ^ 1); CP_COMMIT(); }
        if (jt < jt1) { CP_WAIT(1); } else { CP_WAIT(0); }
        __syncthreads();

        // ---- S = Q K^T  (tf32 single-term) ----
        float sacc[8][4];
#pragma unroll
        for (int j = 0; j < 8; ++j)
#pragma unroll
            for (int e = 0; e < 4; ++e) sacc[j][e] = 0.f;

#pragma unroll
        for (int ks = 0; ks < 8; ++ks) {
            const int kb = ks * 8 + q;
#pragma unroll
            for (int j = 0; j < 8; ++j) {
                const float* kr = (const float*)(st + (j * 8 + g) * 272);
                uint32_t b0 = __float_as_uint(kr[kb]);
                uint32_t b1 = __float_as_uint(kr[kb + 4]);
                mma1688t(sacc[j], qf[ks][0], qf[ks][1], qf[ks][2], qf[ks][3], b0, b1);
            }
        }

        // ---- mask + exp + pack P (bf16 hi/lo) ----
        const bool needMask = (jt >= 2 * it);
        uint32_t ph[8][2], pl[8][2];
#pragma unroll
        for (int j = 0; j < 8; ++j) {
            float e0 = sacc[j][0], e1 = sacc[j][1];
            float e2 = sacc[j][2], e3 = sacc[j][3];
            if (needMask) {
                int c0 = cb + j * 8 + q * 2, c1 = c0 + 1;
                if (c0 > rg0) e0 = -1e30f;
                if (c1 > rg0) e1 = -1e30f;
                if (c0 > rg0 + 8) e2 = -1e30f;
                if (c1 > rg0 + 8) e3 = -1e30f;
            }
            float p0 = ex2f_fast(e0), p1 = ex2f_fast(e1);
            float p2 = ex2f_fast(e2), p3 = ex2f_fast(e3);
            l0 += p0 + p1;
            l1 += p2 + p3;
            uint32_t h0 = pack_bf16x2(p0, p1);
            uint32_t h1 = pack_bf16x2(p2, p3);
            ph[j][0] = h0;
            ph[j][1] = h1;
            pl[j][0] = pack_bf16x2(p0 - __uint_as_float(h0 << 16),
                                   p1 - __uint_as_float(h0 & 0xffff0000u));
            pl[j][1] = pack_bf16x2(p2 - __uint_as_float(h1 << 16),
                                   p3 - __uint_as_float(h1 & 0xffff0000u));
        }

        // ---- O += P V  (bf16 hi/lo 3-term) ----
        const __nv_bfloat16* VThs = (const __nv_bfloat16*)(st + 17408);
        const __nv_bfloat16* VTls = (const __nv_bfloat16*)(st + 26624);
#pragma unroll
        for (int s = 0; s < 4; ++s) {
            uint32_t ah2[4] = { ph[2 * s][0], ph[2 * s][1],
                                ph[2 * s + 1][0], ph[2 * s + 1][1] };
            uint32_t al2[4] = { pl[2 * s][0], pl[2 * s][1],
                                pl[2 * s + 1][0], pl[2 * s + 1][1] };
            const int kb = s * 16 + q * 2;
#pragma unroll
            for (int j = 0; j < 8; ++j) {
                const int n = j * 8 + g;
                uint32_t bh0 = *(const uint32_t*)&VThs[n * 72 + kb];
                uint32_t bh1 = *(const uint32_t*)&VThs[n * 72 + kb + 8];
                uint32_t bl0 = *(const uint32_t*)&VTls[n * 72 + kb];
                uint32_t bl1 = *(const uint32_t*)&VTls[n * 72 + kb + 8];
                mma16816(o[j], ah2, bh0, bh1);
                mma16816(o[j], ah2, bl0, bl1);
                mma16816(o[j], al2, bh0, bh1);
            }
        }
        __syncthreads();   // all reads of buf done before it is refilled
    }

    // ---- reduce l, normalize, store ----
    l0 += __shfl_xor_sync(0xffffffffu, l0, 1, 4);
    l0 += __shfl_xor_sync(0xffffffffu, l0, 2, 4);
    l1 += __shfl_xor_sync(0xffffffffu, l1, 1, 4);
    l1 += __shfl_xor_sync(0xffffffffu, l1, 2, 4);
    const float inv0 = 1.0f / l0, inv1 = 1.0f / l1;

    float* og = out + ((size_t)h * T_TOT + rg0) * 64;
#pragma unroll
    for (int j = 0; j < 8; ++j) {
        int c = j * 8 + q * 2;
        *(float2*)(og + c)          = make_float2(o[j][0] * inv0, o[j][1] * inv0);
        *(float2*)(og + 8 * 64 + c) = make_float2(o[j][2] * inv1, o[j][3] * inv1);
    }
}

// ---------------------------------------------------------------------------
extern "C" void kernel_launch(void* const* d_in, const int* in_sizes, int n_in,
                              void* d_out, int out_size)
{
    (void)in_sizes; (void)n_in; (void)out_size;
    const float* x   = (const float*)d_in[0];
    const float* Wq  = (const float*)d_in[1];
    const float* Wk  = (const float*)d_in[2];
    const float* Wv  = (const float*)d_in[3];
    const float* Wqs = (const float*)d_in[4];
    const float* Wks = (const float*)d_in[5];
    const float* Wvs = (const float*)d_in[6];
    const float* sf  = (const float*)d_in[7];
    float* out = (float*)d_out;

    cudaFuncSetAttribute(proj_kernel,
                         cudaFuncAttributeMaxDynamicSharedMemorySize, PROJ_SMEM);
    cudaFuncSetAttribute(attn_kernel,
                         cudaFuncAttributeMaxDynamicSharedMemorySize, ATTN_SMEM);

    xconv_kernel<<<144, 256>>>(x);
    wconv_kernel<<<dim3(4, 96), 256>>>(Wq, Wk, Wv, Wqs, Wks, Wvs);
    proj_kernel<<<dim3(16, 18), 256, PROJ_SMEM>>>(sf);
    attn_kernel<<<dim3(18, 16), 256, ATTN_SMEM>>>(out);
}

// round 7
// speedup vs baseline: 3.9135x; 1.3726x over previous
#include <cuda_runtime.h>
#include <cuda_bf16.h>
#include <math.h>
#include <cstdint>

// ---------------------------------------------------------------------------
// StatefulCausalAttention  (B=1, H=16, T=2304=128+2048+128, D=1024, dk=dv=64)
// R7: attn: snake-balanced schedule + PV on tf32 single-term with V stored in
//     permuted column order (sigma^-1 on low 3 bits) so S-accumulators feed PV
//     A-fragments directly (no shuffles, no bf16 packing).
//     proj: 512 threads (16 warps, warp tile m32xn48), cp.async stages.
// ---------------------------------------------------------------------------

#define T_TOT 2304
#define D_IN  1024
#define NH    16

// projection outputs
__device__ float g_Qf[NH * T_TOT * 64];   // tf32-rounded, * sf * log2e
__device__ float g_Kf[NH * T_TOT * 64];   // tf32-rounded
__device__ float g_VTf[NH * 64 * T_TOT];  // [h][dv][tau(t)] tf32-rounded, permuted

// frag-shuffled tf32 operands for projection
__device__ float g_Xf[144 * 64 * 2 * 32 * 4];
__device__ float g_Wf[6 * 16 * 64 * 8 * 32 * 4];

// sigma^-1 for the V column permutation (within each 8-block)
__device__ __constant__ int c_siginv[8] = {0, 4, 1, 5, 2, 6, 3, 7};

// ============================ helpers ======================================
__device__ __forceinline__ float ex2f_fast(float x) {
    float y; asm("ex2.approx.f32 %0, %1;" : "=f"(y) : "f"(x)); return y;
}
__device__ __forceinline__ void mma1688t(float* c, uint32_t a0, uint32_t a1,
                                         uint32_t a2, uint32_t a3,
                                         uint32_t b0, uint32_t b1) {
    asm("mma.sync.aligned.m16n8k8.row.col.f32.tf32.tf32.f32 "
        "{%0,%1,%2,%3}, {%4,%5,%6,%7}, {%8,%9}, {%0,%1,%2,%3};"
        : "+f"(c[0]), "+f"(c[1]), "+f"(c[2]), "+f"(c[3])
        : "r"(a0), "r"(a1), "r"(a2), "r"(a3), "r"(b0), "r"(b1));
}
__device__ __forceinline__ uint32_t to_tf32(float f) {
    uint32_t u; asm("cvt.rna.tf32.f32 %0, %1;" : "=r"(u) : "f"(f)); return u;
}
__device__ __forceinline__ uint32_t smem_u32(const void* p) {
    uint32_t a;
    asm("{ .reg .u64 t; cvta.to.shared.u64 t, %1; cvt.u32.u64 %0, t; }" : "=r"(a) : "l"(p));
    return a;
}
#define CP_ASYNC16(dst, src) \
    asm volatile("cp.async.cg.shared.global [%0], [%1], 16;" :: "r"(dst), "l"(src))
#define CP_COMMIT() asm volatile("cp.async.commit_group;" ::: "memory")
#define CP_WAIT(n)  asm volatile("cp.async.wait_group %0;" :: "n"(n) : "memory")

// ============================ prep: X -> frag order ========================
__global__ __launch_bounds__(256) void xconv_kernel(const float* __restrict__ x)
{
    const int strip = blockIdx.x;          // 0..143
    for (int i = threadIdx.x; i < 4096; i += 256) {
        int c = i >> 6, rest = i & 63;
        int t = rest >> 5, ln = rest & 31;
        int g = ln >> 2, q = ln & 3;
        const float* xr = x + (size_t)(strip * 16 + t * 8 + g) * D_IN + c * 16;
        uint4 v;
        v.x = to_tf32(xr[q]);
        v.y = to_tf32(xr[8 + q]);
        v.z = to_tf32(xr[4 + q]);
        v.w = to_tf32(xr[12 + q]);
        ((uint4*)g_Xf)[(size_t)(strip * 64 + c) * 64 + rest] = v;
    }
}

// ============================ prep: W -> frag order ========================
__global__ __launch_bounds__(256) void wconv_kernel(
    const float* __restrict__ Wq,  const float* __restrict__ Wk,  const float* __restrict__ Wv,
    const float* __restrict__ Wqs, const float* __restrict__ Wks, const float* __restrict__ Wvs)
{
    const int cb = blockIdx.x * 16;
    const int mh = blockIdx.y;             // 0..95
    const int mat = mh >> 4, h = mh & 15;
    const float* W;
    switch (mat) {
        case 0: W = Wq;  break; case 1: W = Wqs; break;
        case 2: W = Wk;  break; case 3: W = Wks; break;
        case 4: W = Wv;  break; default: W = Wvs; break;
    }
    W += (size_t)h * D_IN * 64;
    const int tid = threadIdx.x;
    const int ntl = tid >> 5, ln = tid & 31;
    const int g = ln >> 2, r = ln & 3;
    const int n = ntl * 8 + g;
#pragma unroll 4
    for (int ci = 0; ci < 16; ++ci) {
        const int c = cb + ci, k0 = c * 16;
        uint4 v;
        v.x = to_tf32(W[(size_t)(k0 + r) * 64 + n]);
        v.y = to_tf32(W[(size_t)(k0 + 8 + r) * 64 + n]);
        v.z = to_tf32(W[(size_t)(k0 + 4 + r) * 64 + n]);
        v.w = to_tf32(W[(size_t)(k0 + 12 + r) * 64 + n]);
        ((uint4*)g_Wf)[((size_t)(mat * 16 + h) * 64 + c) * 256 + tid] = v;
    }
}

// ============================ projection (tf32 mma, 512 thr) ===============
// block (h, by): rows by*128..+127, q,k,v fused (N=192). 16 warps:
// mi = warp>>2 (m32 = 2 strips), ni = warp&3 (n48). cp.async double buffer.
// stage s at s*20480: A 512 uint4, B 768 uint4; nrm[3][128] at 40960.
#define PROJ_SMEM (40960 + 1536)

__global__ __launch_bounds__(512, 1) void proj_kernel(const float* __restrict__ sf)
{
    extern __shared__ char smc[];
    float* nrm = (float*)(smc + 40960);
    const uint32_t sb = smem_u32(smc);
    const int h  = blockIdx.x;
    const int by = blockIdx.y;
    const int state = (by == 0 || by == 17) ? 1 : 0;
    const int tid = threadIdx.x, warp = tid >> 5, lane = tid & 31;
    const int mi = warp >> 2, ni = warp & 3;
    const int g = lane >> 2, qq = lane & 3;
    const int strip0 = by * 8;

    for (int i = tid; i < 384; i += 512) nrm[i] = 0.f;

    const float* Xfp = g_Xf;
    const float* Wfp = g_Wf;

    float acc[2][6][4];
#pragma unroll
    for (int st = 0; st < 2; ++st)
#pragma unroll
        for (int nt = 0; nt < 6; ++nt)
#pragma unroll
            for (int e = 0; e < 4; ++e) acc[st][nt][e] = 0.f;

    auto issue_stage = [&](int c) {
        const uint32_t sa = sb + (c & 1) * 20480;
#pragma unroll
        for (int i = 0; i < 3; ++i) {
            int slot = tid + i * 512;
            if (slot >= 1280) break;
            if (slot < 512) {
                const float* src = Xfp + ((size_t)((strip0 + (slot >> 6)) * 64 + c) * 64
                                          + (slot & 63)) * 4;
                CP_ASYNC16(sa + slot * 16, src);
            } else {
                int s2 = slot - 512;
                int mat = (s2 >> 8) * 2 + state;
                const float* src = Wfp + (((size_t)(mat * 16 + h) * 64 + c) * 256
                                          + (s2 & 255)) * 4;
                CP_ASYNC16(sa + 8192 + s2 * 16, src);
            }
        }
    };

    issue_stage(0);
    CP_COMMIT();

    for (int c = 0; c < 64; ++c) {
        const char* sa = smc + (c & 1) * 20480;
        if (c + 1 < 64) { issue_stage(c + 1); CP_COMMIT(); CP_WAIT(1); }
        else            { CP_WAIT(0); }
        __syncthreads();

        uint4 Af[2][2], Bf[6];
#pragma unroll
        for (int st = 0; st < 2; ++st)
#pragma unroll
            for (int t = 0; t < 2; ++t)
                Af[st][t] = *(const uint4*)(sa + (((mi * 2 + st) * 2 + t) * 32 + lane) * 16);
#pragma unroll
        for (int nt = 0; nt < 6; ++nt)
            Bf[nt] = *(const uint4*)(sa + 8192 + ((ni * 6 + nt) * 32 + lane) * 16);

#pragma unroll
        for (int s = 0; s < 2; ++s) {
#pragma unroll
            for (int st = 0; st < 2; ++st) {
                uint32_t a0 = s ? Af[st][0].y : Af[st][0].x;
                uint32_t a1 = s ? Af[st][1].y : Af[st][1].x;
                uint32_t a2 = s ? Af[st][0].w : Af[st][0].z;
                uint32_t a3 = s ? Af[st][1].w : Af[st][1].z;
#pragma unroll
                for (int nt = 0; nt < 6; ++nt) {
                    uint32_t b0 = s ? Bf[nt].y : Bf[nt].x;
                    uint32_t b1 = s ? Bf[nt].w : Bf[nt].z;
                    mma1688t(acc[st][nt], a0, a1, a2, a3, b0, b1);
                }
            }
        }
        __syncthreads();
    }

    // ---- norm partials ----
#pragma unroll
    for (int st = 0; st < 2; ++st) {
#pragma unroll
        for (int nt = 0; nt < 6; ++nt) {
            int mat = (ni * 6 + nt) >> 3;
            int rl0 = (mi * 2 + st) * 16 + g;
            atomicAdd(&nrm[mat * 128 + rl0],
                      acc[st][nt][0] * acc[st][nt][0] + acc[st][nt][1] * acc[st][nt][1]);
            atomicAdd(&nrm[mat * 128 + rl0 + 8],
                      acc[st][nt][2] * acc[st][nt][2] + acc[st][nt][3] * acc[st][nt][3]);
        }
    }
    __syncthreads();

    // ---- scale + store: Q/K tf32 fp32; V tf32 fp32 transposed + permuted ----
    const float qs = sf[h] * 1.44269504088896340736f;
#pragma unroll
    for (int st = 0; st < 2; ++st) {
        const int rl0 = (mi * 2 + st) * 16 + g;
        const int rg0 = by * 128 + rl0;
#pragma unroll
        for (int nt = 0; nt < 6; ++nt) {
            const int ntg = ni * 6 + nt;
            const int mat = ntg >> 3;
            const int ntl = ntg & 7;
            const float mult = (mat == 0) ? qs : 1.0f;
            float inv0 = mult / fmaxf(sqrtf(nrm[mat * 128 + rl0]),     1e-12f);
            float inv1 = mult / fmaxf(sqrtf(nrm[mat * 128 + rl0 + 8]), 1e-12f);
            float v0 = acc[st][nt][0] * inv0, v1 = acc[st][nt][1] * inv0;
            float v2 = acc[st][nt][2] * inv1, v3 = acc[st][nt][3] * inv1;
            const int col = ntl * 8 + qq * 2;
            if (mat < 2) {
                float* dst = (mat == 0 ? g_Qf : g_Kf) + (size_t)h * T_TOT * 64;
                uint2 w0 = make_uint2(to_tf32(v0), to_tf32(v1));
                uint2 w1 = make_uint2(to_tf32(v2), to_tf32(v3));
                *(uint2*)(dst + (size_t)(rg0    ) * 64 + col) = w0;
                *(uint2*)(dst + (size_t)(rg0 + 8) * 64 + col) = w1;
            } else {
                // V: element (t=rr, dv=cc) -> g_VTf[h][cc][ (rr&~7) | siginv[rr&7] ]
                float* dv = g_VTf + (size_t)h * 64 * T_TOT;
                float vv[4] = {v0, v1, v2, v3};
                const int tperm = (rg0 & ~7) | c_siginv[rg0 & 7];
#pragma unroll
                for (int e = 0; e < 4; ++e) {
                    int cc = col + (e & 1);
                    int rr = tperm + (e >> 1) * 8;
                    dv[(size_t)cc * T_TOT + rr] = __uint_as_float(to_tf32(vv[e]));
                }
            }
        }
    }
}

// ============================ attention v3 =================================
// 256 threads, 8 warps x 16 q-rows, kv-tile 64, 2 CTAs/SM.
// Snake-balanced 1-D schedule: rank r=(L<152?L:439-L); h=r%16; it=17-r/16.
// Stage (34816 B): K f32 [64][68] @0 ; V f32 [64 dv][68] @17408 (permuted t).
// PV on tf32: S accumulators ARE the A-fragments (V permutation absorbs the
// k-order mismatch); D-frag layout of PV equals S layout -> store unchanged.
#define STAGE_B 34816
#define ATTN_SMEM (2 * STAGE_B)

__global__ __launch_bounds__(256, 2) void attn_kernel(float* __restrict__ out)
{
    extern __shared__ char smc[];
    const uint32_t sb = smem_u32(smc);
    const int L = blockIdx.x;
    const int r = (L < 152) ? L : 439 - L;
    const int h  = r & 15;
    const int it = 17 - (r >> 4);
    const int rb = it * 128;
    const int tid = threadIdx.x;
    const int warp = tid >> 5, lane = tid & 31;
    const int g = lane >> 2, q = lane & 3;
    const int rg0 = rb + warp * 16 + g;

    // ---- Q fragments (tf32 fp32, registers) ----
    uint32_t qf[8][4];
    {
        const float* Qf = g_Qf + ((size_t)h * T_TOT + rg0) * 64;
#pragma unroll
        for (int ks = 0; ks < 8; ++ks) {
            int k = ks * 8 + q;
            qf[ks][0] = __float_as_uint(Qf[k]);
            qf[ks][1] = __float_as_uint(Qf[8 * 64 + k]);
            qf[ks][2] = __float_as_uint(Qf[k + 4]);
            qf[ks][3] = __float_as_uint(Qf[8 * 64 + k + 4]);
        }
    }

    float o[8][4];
#pragma unroll
    for (int j = 0; j < 8; ++j)
#pragma unroll
        for (int e = 0; e < 4; ++e) o[j][e] = 0.f;
    float l0 = 0.f, l1 = 0.f;

    const int jt0 = (it == 17) ? 2 : 0;
    const int jt1 = 2 * it + 1;

    auto issue_stage = [&](int jt, int buf) {
        const int cb = jt * 64;
        const uint32_t stb = sb + buf * STAGE_B;
#pragma unroll
        for (int i = 0; i < 8; ++i) {
            int slot = tid + i * 256;
            int arr = slot >> 10;              // 0=K 1=V
            int s2 = slot & 1023;
            int row = s2 >> 4, ch = s2 & 15;
            const float* src = (arr == 0)
                ? g_Kf  + ((size_t)h * T_TOT + cb + row) * 64 + ch * 4
                : g_VTf + (size_t)h * 64 * T_TOT + (size_t)row * T_TOT + cb + ch * 4;
            CP_ASYNC16(stb + arr * 17408 + row * 272 + ch * 16, src);
        }
    };

    issue_stage(jt0, 0);
    CP_COMMIT();

    for (int jt = jt0; jt <= jt1; ++jt) {
        const int cb = jt * 64;
        const int buf = (jt - jt0) & 1;
        const char* st = smc + buf * STAGE_B;

        if (jt < jt1) { issue_stage(jt + 1, buf ^ 1); CP_COMMIT(); CP_WAIT(1); }
        else          { CP_WAIT(0); }
        __syncthreads();

        // ---- S = Q K^T (tf32) ----
        float sacc[8][4];
#pragma unroll
        for (int j = 0; j < 8; ++j)
#pragma unroll
            for (int e = 0; e < 4; ++e) sacc[j][e] = 0.f;

#pragma unroll
        for (int ks = 0; ks < 8; ++ks) {
            const int kb = ks * 8 + q;
#pragma unroll
            for (int j = 0; j < 8; ++j) {
                const float* kr = (const float*)(st + (j * 8 + g) * 272);
                uint32_t b0 = __float_as_uint(kr[kb]);
                uint32_t b1 = __float_as_uint(kr[kb + 4]);
                mma1688t(sacc[j], qf[ks][0], qf[ks][1], qf[ks][2], qf[ks][3], b0, b1);
            }
        }

        // ---- mask + exp (P stays in sacc layout; becomes PV A-frags) ----
        const bool needMask = (jt >= 2 * it);
        uint32_t pa[8][4];
#pragma unroll
        for (int j = 0; j < 8; ++j) {
            float e0 = sacc[j][0], e1 = sacc[j][1];
            float e2 = sacc[j][2], e3 = sacc[j][3];
            if (needMask) {
                int c0 = cb + j * 8 + q * 2, c1 = c0 + 1;
                if (c0 > rg0) e0 = -1e30f;
                if (c1 > rg0) e1 = -1e30f;
                if (c0 > rg0 + 8) e2 = -1e30f;
                if (c1 > rg0 + 8) e3 = -1e30f;
            }
            float p0 = ex2f_fast(e0), p1 = ex2f_fast(e1);
            float p2 = ex2f_fast(e2), p3 = ex2f_fast(e3);
            l0 += p0 + p1;
            l1 += p2 + p3;
            // A-frag (k-order absorbed by V permutation): a0=p0 a1=p2 a2=p1 a3=p3
            pa[j][0] = to_tf32(p0);
            pa[j][1] = to_tf32(p2);
            pa[j][2] = to_tf32(p1);
            pa[j][3] = to_tf32(p3);
        }

        // ---- O += P V (tf32; V rows pre-permuted) ----
        const char* vb = st + 17408;
#pragma unroll
        for (int ks = 0; ks < 8; ++ks) {       // ks = kv 8-block (= P j-block)
            const int tb = ks * 8;
#pragma unroll
            for (int j = 0; j < 8; ++j) {      // j = dv n-tile
                const float* vr = (const float*)(vb + (j * 8 + g) * 272);
                uint32_t b0 = __float_as_uint(vr[tb + q]);
                uint32_t b1 = __float_as_uint(vr[tb + q + 4]);
                mma1688t(o[j], pa[ks][0], pa[ks][1], pa[ks][2], pa[ks][3], b0, b1);
            }
        }
        __syncthreads();   // all reads of buf done before refill
    }

    // ---- reduce l, normalize, store ----
    l0 += __shfl_xor_sync(0xffffffffu, l0, 1, 4);
    l0 += __shfl_xor_sync(0xffffffffu, l0, 2, 4);
    l1 += __shfl_xor_sync(0xffffffffu, l1, 1, 4);
    l1 += __shfl_xor_sync(0xffffffffu, l1, 2, 4);
    const float inv0 = 1.0f / l0, inv1 = 1.0f / l1;

    float* og = out + ((size_t)h * T_TOT + rg0) * 64;
#pragma unroll
    for (int j = 0; j < 8; ++j) {
        int c = j * 8 + q * 2;
        *(float2*)(og + c)          = make_float2(o[j][0] * inv0, o[j][1] * inv0);
        *(float2*)(og + 8 * 64 + c) = make_float2(o[j][2] * inv1, o[j][3] * inv1);
    }
}

// ---------------------------------------------------------------------------
extern "C" void kernel_launch(void* const* d_in, const int* in_sizes, int n_in,
                              void* d_out, int out_size)
{
    (void)in_sizes; (void)n_in; (void)out_size;
    const float* x   = (const float*)d_in[0];
    const float* Wq  = (const float*)d_in[1];
    const float* Wk  = (const float*)d_in[2];
    const float* Wv  = (const float*)d_in[3];
    const float* Wqs = (const float*)d_in[4];
    const float* Wks = (const float*)d_in[5];
    const float* Wvs = (const float*)d_in[6];
    const float* sf  = (const float*)d_in[7];
    float* out = (float*)d_out;

    cudaFuncSetAttribute(proj_kernel,
                         cudaFuncAttributeMaxDynamicSharedMemorySize, PROJ_SMEM);
    cudaFuncSetAttribute(attn_kernel,
                         cudaFuncAttributeMaxDynamicSharedMemorySize, ATTN_SMEM);

    xconv_kernel<<<144, 256>>>(x);
    wconv_kernel<<<dim3(4, 96), 256>>>(Wq, Wk, Wv, Wqs, Wks, Wvs);
    proj_kernel<<<dim3(16, 18), 512, PROJ_SMEM>>>(sf);
    attn_kernel<<<288, 256, ATTN_SMEM>>>(out);
}

// round 8
// speedup vs baseline: 4.3617x; 1.1145x over previous
#include <cuda_runtime.h>
#include <cuda_bf16.h>
#include <math.h>
#include <cstdint>

// ---------------------------------------------------------------------------
// StatefulCausalAttention  (B=1, H=16, T=2304=128+2048+128, D=1024, dk=dv=64)
// R8: attn: LDS.64 B-fragments via contraction-order relabel (k-lane q ->
//     logical 2q,2q+1); V stored natural order (relabel absorbs R7's sigma);
//     288B smem row stride (conflict-free). proj: 4-stage cp.async ring.
//     xconv+wconv merged into one launch.
// ---------------------------------------------------------------------------

#define T_TOT 2304
#define D_IN  1024
#define NH    16

// projection outputs
__device__ float g_Qf[NH * T_TOT * 64];   // tf32-rounded, * sf * log2e
__device__ float g_Kf[NH * T_TOT * 64];   // tf32-rounded
__device__ float g_VTf[NH * 64 * T_TOT];  // [h][dv][t] tf32-rounded (natural)

// frag-shuffled tf32 operands for projection
__device__ float g_Xf[144 * 64 * 2 * 32 * 4];
__device__ float g_Wf[6 * 16 * 64 * 8 * 32 * 4];

// ============================ helpers ======================================
__device__ __forceinline__ float ex2f_fast(float x) {
    float y; asm("ex2.approx.f32 %0, %1;" : "=f"(y) : "f"(x)); return y;
}
__device__ __forceinline__ void mma1688t(float* c, uint32_t a0, uint32_t a1,
                                         uint32_t a2, uint32_t a3,
                                         uint32_t b0, uint32_t b1) {
    asm("mma.sync.aligned.m16n8k8.row.col.f32.tf32.tf32.f32 "
        "{%0,%1,%2,%3}, {%4,%5,%6,%7}, {%8,%9}, {%0,%1,%2,%3};"
        : "+f"(c[0]), "+f"(c[1]), "+f"(c[2]), "+f"(c[3])
        : "r"(a0), "r"(a1), "r"(a2), "r"(a3), "r"(b0), "r"(b1));
}
__device__ __forceinline__ uint32_t to_tf32(float f) {
    uint32_t u; asm("cvt.rna.tf32.f32 %0, %1;" : "=r"(u) : "f"(f)); return u;
}
__device__ __forceinline__ uint32_t smem_u32(const void* p) {
    uint32_t a;
    asm("{ .reg .u64 t; cvta.to.shared.u64 t, %1; cvt.u32.u64 %0, t; }" : "=r"(a) : "l"(p));
    return a;
}
#define CP_ASYNC16(dst, src) \
    asm volatile("cp.async.cg.shared.global [%0], [%1], 16;" :: "r"(dst), "l"(src))
#define CP_COMMIT() asm volatile("cp.async.commit_group;" ::: "memory")
#define CP_WAIT(n)  asm volatile("cp.async.wait_group %0;" :: "n"(n) : "memory")

// ============================ prep: X + W -> frag order (merged) ===========
__global__ __launch_bounds__(256) void conv_kernel(
    const float* __restrict__ x,
    const float* __restrict__ Wq,  const float* __restrict__ Wk,  const float* __restrict__ Wv,
    const float* __restrict__ Wqs, const float* __restrict__ Wks, const float* __restrict__ Wvs)
{
    const int bid = blockIdx.x;
    if (bid < 144) {
        const int strip = bid;
        for (int i = threadIdx.x; i < 4096; i += 256) {
            int c = i >> 6, rest = i & 63;
            int t = rest >> 5, ln = rest & 31;
            int g = ln >> 2, q = ln & 3;
            const float* xr = x + (size_t)(strip * 16 + t * 8 + g) * D_IN + c * 16;
            uint4 v;
            v.x = to_tf32(xr[q]);
            v.y = to_tf32(xr[8 + q]);
            v.z = to_tf32(xr[4 + q]);
            v.w = to_tf32(xr[12 + q]);
            ((uint4*)g_Xf)[(size_t)(strip * 64 + c) * 64 + rest] = v;
        }
    } else {
        const int wb = bid - 144;          // 0..383
        const int cb = (wb & 3) * 16;
        const int mh = wb >> 2;            // 0..95
        const int mat = mh >> 4, h = mh & 15;
        const float* W;
        switch (mat) {
            case 0: W = Wq;  break; case 1: W = Wqs; break;
            case 2: W = Wk;  break; case 3: W = Wks; break;
            case 4: W = Wv;  break; default: W = Wvs; break;
        }
        W += (size_t)h * D_IN * 64;
        const int tid = threadIdx.x;
        const int ntl = tid >> 5, ln = tid & 31;
        const int g = ln >> 2, r = ln & 3;
        const int n = ntl * 8 + g;
#pragma unroll 4
        for (int ci = 0; ci < 16; ++ci) {
            const int c = cb + ci, k0 = c * 16;
            uint4 v;
            v.x = to_tf32(W[(size_t)(k0 + r) * 64 + n]);
            v.y = to_tf32(W[(size_t)(k0 + 8 + r) * 64 + n]);
            v.z = to_tf32(W[(size_t)(k0 + 4 + r) * 64 + n]);
            v.w = to_tf32(W[(size_t)(k0 + 12 + r) * 64 + n]);
            ((uint4*)g_Wf)[((size_t)(mat * 16 + h) * 64 + c) * 256 + tid] = v;
        }
    }
}

// ============================ projection (tf32 mma, 512 thr) ===============
// 4-stage cp.async ring (depth-3 prefetch). Stage s at s*20480:
// A 512 uint4, B 768 uint4; nrm[3][128] at 81920.
#define PROJ_SMEM (81920 + 1536)

__global__ __launch_bounds__(512, 1) void proj_kernel(const float* __restrict__ sf)
{
    extern __shared__ char smc[];
    float* nrm = (float*)(smc + 81920);
    const uint32_t sb = smem_u32(smc);
    const int h  = blockIdx.x;
    const int by = blockIdx.y;
    const int state = (by == 0 || by == 17) ? 1 : 0;
    const int tid = threadIdx.x, warp = tid >> 5, lane = tid & 31;
    const int mi = warp >> 2, ni = warp & 3;
    const int g = lane >> 2, qq = lane & 3;
    const int strip0 = by * 8;

    for (int i = tid; i < 384; i += 512) nrm[i] = 0.f;

    float acc[2][6][4];
#pragma unroll
    for (int st = 0; st < 2; ++st)
#pragma unroll
        for (int nt = 0; nt < 6; ++nt)
#pragma unroll
            for (int e = 0; e < 4; ++e) acc[st][nt][e] = 0.f;

    auto issue_stage = [&](int c) {
        const uint32_t sa = sb + (c & 3) * 20480;
#pragma unroll
        for (int i = 0; i < 3; ++i) {
            int slot = tid + i * 512;
            if (slot >= 1280) break;
            if (slot < 512) {
                const float* src = g_Xf + ((size_t)((strip0 + (slot >> 6)) * 64 + c) * 64
                                           + (slot & 63)) * 4;
                CP_ASYNC16(sa + slot * 16, src);
            } else {
                int s2 = slot - 512;
                int mat = (s2 >> 8) * 2 + state;
                const float* src = g_Wf + (((size_t)(mat * 16 + h) * 64 + c) * 256
                                           + (s2 & 255)) * 4;
                CP_ASYNC16(sa + 8192 + s2 * 16, src);
            }
        }
    };

    issue_stage(0); CP_COMMIT();
    issue_stage(1); CP_COMMIT();
    issue_stage(2); CP_COMMIT();

    for (int c = 0; c < 64; ++c) {
        if (c < 62)       CP_WAIT(2);
        else if (c == 62) CP_WAIT(1);
        else              CP_WAIT(0);
        __syncthreads();

        const char* sa = smc + (c & 3) * 20480;
        uint4 Af[2][2], Bf[6];
#pragma unroll
        for (int st = 0; st < 2; ++st)
#pragma unroll
            for (int t = 0; t < 2; ++t)
                Af[st][t] = *(const uint4*)(sa + (((mi * 2 + st) * 2 + t) * 32 + lane) * 16);
#pragma unroll
        for (int nt = 0; nt < 6; ++nt)
            Bf[nt] = *(const uint4*)(sa + 8192 + ((ni * 6 + nt) * 32 + lane) * 16);

#pragma unroll
        for (int s = 0; s < 2; ++s) {
#pragma unroll
            for (int st = 0; st < 2; ++st) {
                uint32_t a0 = s ? Af[st][0].y : Af[st][0].x;
                uint32_t a1 = s ? Af[st][1].y : Af[st][1].x;
                uint32_t a2 = s ? Af[st][0].w : Af[st][0].z;
                uint32_t a3 = s ? Af[st][1].w : Af[st][1].z;
#pragma unroll
                for (int nt = 0; nt < 6; ++nt) {
                    uint32_t b0 = s ? Bf[nt].y : Bf[nt].x;
                    uint32_t b1 = s ? Bf[nt].w : Bf[nt].z;
                    mma1688t(acc[st][nt], a0, a1, a2, a3, b0, b1);
                }
            }
        }
        if (c + 3 < 64) { issue_stage(c + 3); CP_COMMIT(); }
    }

    // ---- norm partials ----
#pragma unroll
    for (int st = 0; st < 2; ++st) {
#pragma unroll
        for (int nt = 0; nt < 6; ++nt) {
            int mat = (ni * 6 + nt) >> 3;
            int rl0 = (mi * 2 + st) * 16 + g;
            atomicAdd(&nrm[mat * 128 + rl0],
                      acc[st][nt][0] * acc[st][nt][0] + acc[st][nt][1] * acc[st][nt][1]);
            atomicAdd(&nrm[mat * 128 + rl0 + 8],
                      acc[st][nt][2] * acc[st][nt][2] + acc[st][nt][3] * acc[st][nt][3]);
        }
    }
    __syncthreads();

    // ---- scale + store: Q/K tf32 fp32; V tf32 fp32 transposed (natural) ----
    const float qs = sf[h] * 1.44269504088896340736f;
#pragma unroll
    for (int st = 0; st < 2; ++st) {
        const int rl0 = (mi * 2 + st) * 16 + g;
        const int rg0 = by * 128 + rl0;
#pragma unroll
        for (int nt = 0; nt < 6; ++nt) {
            const int ntg = ni * 6 + nt;
            const int mat = ntg >> 3;
            const int ntl = ntg & 7;
            const float mult = (mat == 0) ? qs : 1.0f;
            float inv0 = mult / fmaxf(sqrtf(nrm[mat * 128 + rl0]),     1e-12f);
            float inv1 = mult / fmaxf(sqrtf(nrm[mat * 128 + rl0 + 8]), 1e-12f);
            float v0 = acc[st][nt][0] * inv0, v1 = acc[st][nt][1] * inv0;
            float v2 = acc[st][nt][2] * inv1, v3 = acc[st][nt][3] * inv1;
            const int col = ntl * 8 + qq * 2;
            if (mat < 2) {
                float* dst = (mat == 0 ? g_Qf : g_Kf) + (size_t)h * T_TOT * 64;
                uint2 w0 = make_uint2(to_tf32(v0), to_tf32(v1));
                uint2 w1 = make_uint2(to_tf32(v2), to_tf32(v3));
                *(uint2*)(dst + (size_t)(rg0    ) * 64 + col) = w0;
                *(uint2*)(dst + (size_t)(rg0 + 8) * 64 + col) = w1;
            } else {
                float* dv = g_VTf + (size_t)h * 64 * T_TOT;
                float vv[4] = {v0, v1, v2, v3};
#pragma unroll
                for (int e = 0; e < 4; ++e) {
                    int cc = col + (e & 1);
                    int rr = rg0 + (e >> 1) * 8;
                    dv[(size_t)cc * T_TOT + rr] = __uint_as_float(to_tf32(vv[e]));
                }
            }
        }
    }
}

// ============================ attention v4 =================================
// 256 threads, 8 warps x 16 q-rows, kv-tile 64, 2 CTAs/SM, snake schedule.
// Contraction relabel: mma k-lane q handles logical k = 2q, 2q+1 ->
// B-fragments are adjacent float2 (LDS.64). Row stride 288 B: word index
// (8g+8ks+2q) mod 32 -> conflict-free per quarter-warp phase.
// Stage (36864 B): K f32 [64 rows][288B] @0 ; V f32 [64 dv][288B] @18432.
#define STAGE_B 36864
#define ATTN_SMEM (2 * STAGE_B)

__global__ __launch_bounds__(256, 2) void attn_kernel(float* __restrict__ out)
{
    extern __shared__ char smc[];
    const uint32_t sb = smem_u32(smc);
    const int L = blockIdx.x;
    const int r = (L < 152) ? L : 439 - L;
    const int h  = r & 15;
    const int it = 17 - (r >> 4);
    const int rb = it * 128;
    const int tid = threadIdx.x;
    const int warp = tid >> 5, lane = tid & 31;
    const int g = lane >> 2, q = lane & 3;
    const int rg0 = rb + warp * 16 + g;

    // ---- Q fragments: k-lane q <-> logical k = 2q, 2q+1 (adjacent pairs) ----
    uint32_t qf[8][4];
    {
        const float* Qf = g_Qf + ((size_t)h * T_TOT + rg0) * 64;
#pragma unroll
        for (int ks = 0; ks < 8; ++ks) {
            float2 lo = *(const float2*)&Qf[ks * 8 + 2 * q];
            float2 hi = *(const float2*)&Qf[8 * 64 + ks * 8 + 2 * q];
            qf[ks][0] = __float_as_uint(lo.x);   // a0: row g,   k-lane q
            qf[ks][1] = __float_as_uint(hi.x);   // a1: row g+8, k-lane q
            qf[ks][2] = __float_as_uint(lo.y);   // a2: row g,   k-lane q+4
            qf[ks][3] = __float_as_uint(hi.y);   // a3: row g+8, k-lane q+4
        }
    }

    float o[8][4];
#pragma unroll
    for (int j = 0; j < 8; ++j)
#pragma unroll
        for (int e = 0; e < 4; ++e) o[j][e] = 0.f;
    float l0 = 0.f, l1 = 0.f;

    const int jt0 = (it == 17) ? 2 : 0;
    const int jt1 = 2 * it + 1;

    auto issue_stage = [&](int jt, int buf) {
        const int cb = jt * 64;
        const uint32_t stb = sb + buf * STAGE_B;
#pragma unroll
        for (int i = 0; i < 8; ++i) {
            int slot = tid + i * 256;
            int arr = slot >> 10;              // 0=K 1=V
            int s2 = slot & 1023;
            int row = s2 >> 4, ch = s2 & 15;
            const float* src = (arr == 0)
                ? g_Kf  + ((size_t)h * T_TOT + cb + row) * 64 + ch * 4
                : g_VTf + (size_t)h * 64 * T_TOT + (size_t)row * T_TOT + cb + ch * 4;
            CP_ASYNC16(stb + arr * 18432 + row * 288 + ch * 16, src);
        }
    };

    issue_stage(jt0, 0);
    CP_COMMIT();

    for (int jt = jt0; jt <= jt1; ++jt) {
        const int cb = jt * 64;
        const int buf = (jt - jt0) & 1;
        const char* st = smc + buf * STAGE_B;

        if (jt < jt1) { issue_stage(jt + 1, buf ^ 1); CP_COMMIT(); CP_WAIT(1); }
        else          { CP_WAIT(0); }
        __syncthreads();

        // ---- S = Q K^T (tf32, LDS.64 B-frags) ----
        float sacc[8][4];
#pragma unroll
        for (int j = 0; j < 8; ++j)
#pragma unroll
            for (int e = 0; e < 4; ++e) sacc[j][e] = 0.f;

#pragma unroll
        for (int ks = 0; ks < 8; ++ks) {
#pragma unroll
            for (int j = 0; j < 8; ++j) {
                const float2* kr = (const float2*)(st + (j * 8 + g) * 288);
                float2 b = kr[ks * 4 + q];
                mma1688t(sacc[j], qf[ks][0], qf[ks][1], qf[ks][2], qf[ks][3],
                         __float_as_uint(b.x), __float_as_uint(b.y));
            }
        }

        // ---- mask + exp (sacc layout = PV A-frag layout under relabel) ----
        const bool needMask = (jt >= 2 * it);
        uint32_t pa[8][4];
#pragma unroll
        for (int j = 0; j < 8; ++j) {
            float e0 = sacc[j][0], e1 = sacc[j][1];
            float e2 = sacc[j][2], e3 = sacc[j][3];
            if (needMask) {
                int c0 = cb + j * 8 + q * 2, c1 = c0 + 1;
                if (c0 > rg0) e0 = -1e30f;
                if (c1 > rg0) e1 = -1e30f;
                if (c0 > rg0 + 8) e2 = -1e30f;
                if (c1 > rg0 + 8) e3 = -1e30f;
            }
            float p0 = ex2f_fast(e0), p1 = ex2f_fast(e1);
            float p2 = ex2f_fast(e2), p3 = ex2f_fast(e3);
            l0 += p0 + p1;
            l1 += p2 + p3;
            // A-frag: k-lane q <-> kv col 2q; k-lane q+4 <-> 2q+1
            pa[j][0] = to_tf32(p0);
            pa[j][1] = to_tf32(p2);
            pa[j][2] = to_tf32(p1);
            pa[j][3] = to_tf32(p3);
        }

        // ---- O += P V (tf32; V natural order, LDS.64 B-frags) ----
        const char* vb = st + 18432;
#pragma unroll
        for (int ks = 0; ks < 8; ++ks) {
#pragma unroll
            for (int j = 0; j < 8; ++j) {
                const float2* vr = (const float2*)(vb + (j * 8 + g) * 288);
                float2 b = vr[ks * 4 + q];
                mma1688t(o[j], pa[ks][0], pa[ks][1], pa[ks][2], pa[ks][3],
                         __float_as_uint(b.x), __float_as_uint(b.y));
            }
        }
        __syncthreads();   // all reads of buf done before refill
    }

    // ---- reduce l, normalize, store ----
    l0 += __shfl_xor_sync(0xffffffffu, l0, 1, 4);
    l0 += __shfl_xor_sync(0xffffffffu, l0, 2, 4);
    l1 += __shfl_xor_sync(0xffffffffu, l1, 1, 4);
    l1 += __shfl_xor_sync(0xffffffffu, l1, 2, 4);
    const float inv0 = 1.0f / l0, inv1 = 1.0f / l1;

    float* og = out + ((size_t)h * T_TOT + rg0) * 64;
#pragma unroll
    for (int j = 0; j < 8; ++j) {
        int c = j * 8 + q * 2;
        *(float2*)(og + c)          = make_float2(o[j][0] * inv0, o[j][1] * inv0);
        *(float2*)(og + 8 * 64 + c) = make_float2(o[j][2] * inv1, o[j][3] * inv1);
    }
}

// ---------------------------------------------------------------------------
extern "C" void kernel_launch(void* const* d_in, const int* in_sizes, int n_in,
                              void* d_out, int out_size)
{
    (void)in_sizes; (void)n_in; (void)out_size;
    const float* x   = (const float*)d_in[0];
    const float* Wq  = (const float*)d_in[1];
    const float* Wk  = (const float*)d_in[2];
    const float* Wv  = (const float*)d_in[3];
    const float* Wqs = (const float*)d_in[4];
    const float* Wks = (const float*)d_in[5];
    const float* Wvs = (const float*)d_in[6];
    const float* sf  = (const float*)d_in[7];
    float* out = (float*)d_out;

    cudaFuncSetAttribute(proj_kernel,
                         cudaFuncAttributeMaxDynamicSharedMemorySize, PROJ_SMEM);
    cudaFuncSetAttribute(attn_kernel,
                         cudaFuncAttributeMaxDynamicSharedMemorySize, ATTN_SMEM);

    conv_kernel<<<528, 256>>>(x, Wq, Wk, Wv, Wqs, Wks, Wvs);
    proj_kernel<<<dim3(16, 18), 512, PROJ_SMEM>>>(sf);
    attn_kernel<<<288, 256, ATTN_SMEM>>>(out);
}